// round 3
// baseline (speedup 1.0000x reference)
#include <cuda_runtime.h>
#include <cstdint>

// GAGKNNQueryAndGroup on GB300.
// LAMBDA = 0.5 -> lam == 1-lam: rescale multiplies every distance by 0.5
// (uniform), ordering is plain squared-distance KNN; components inputs dead.
//
// R3: exact 1-D pruning. Points are sorted by x per batch (bitonic, device
// scratch). Each query warp binary-searches its x, expands left/right taking
// the nearer frontier, and stops a side when fl(dx^2)*0.999999 > thr -- a
// provably safe bound (computed d >= fl(dx^2)*(1-2u)). Insert key is
// (dist_bits<<32)|orig_idx, so the final top-32 is processing-order invariant
// (ties resolved by index, matching stable argsort) => result stays exact.
// Near-sorted-by-distance arrival also cuts inserts from ~210 to ~60/query.

#define FULLMASK 0xffffffffu

constexpr int BATCH  = 4;
constexpr int NPTS   = 8192;
constexpr int NQUERY = 2048;
constexpr int NCH    = 64;
constexpr int NS     = 32;
constexpr int QPB    = 32;                 // queries (warps) per knn block
constexpr int KNN_THREADS = QPB * 32;      // 1024
constexpr float STOP_MARGIN = 0.999999f;   // >> 2*2^-24, conservative

__device__ int    g_knn_idx[BATCH * NQUERY * NS];
__device__ float4 g_pts4[BATCH * NPTS];    // sorted by x: {x,y,z,idx_bits}

// ---------------------------------------------------------------- sort ----
__global__ void sort_kernel(const float* __restrict__ xyz) {
    extern __shared__ unsigned long long a[];   // 64KB
    const int b = blockIdx.x;
    const int tid = threadIdx.x;

    for (int i = tid; i < NPTS; i += blockDim.x) {
        unsigned ub = __float_as_uint(xyz[((size_t)b * NPTS + i) * 3]);
        unsigned key = (ub & 0x80000000u) ? ~ub : (ub | 0x80000000u);
        a[i] = ((unsigned long long)key << 32) | (unsigned)i;
    }
    __syncthreads();

    for (int k = 2; k <= NPTS; k <<= 1) {
        for (int j = k >> 1; j > 0; j >>= 1) {
            for (int i = tid; i < NPTS; i += blockDim.x) {
                int ixj = i ^ j;
                if (ixj > i) {
                    unsigned long long x0 = a[i], x1 = a[ixj];
                    bool up = ((i & k) == 0);
                    if ((x0 > x1) == up) { a[i] = x1; a[ixj] = x0; }
                }
            }
            __syncthreads();
        }
    }

    for (int i = tid; i < NPTS; i += blockDim.x) {
        int orig = (int)(unsigned)(a[i] & 0xffffffffu);
        const float* p = xyz + ((size_t)b * NPTS + orig) * 3;
        float4 o;
        o.x = p[0]; o.y = p[1]; o.z = p[2];
        o.w = __int_as_float(orig);
        g_pts4[(size_t)b * NPTS + i] = o;
    }
}

// ----------------------------------------------------------------- knn ----
__device__ __forceinline__ float sqdist(float qx, float qy, float qz,
                                        float x, float y, float z) {
    // No FMA contraction: matches reference (diff*diff then sum) bit-exactly.
    float dx = qx - x, dy = qy - y, dz = qz - z;
    return __fadd_rn(__fadd_rn(__fmul_rn(dx, dx), __fmul_rn(dy, dy)),
                     __fmul_rn(dz, dz));
}

__device__ __forceinline__ void warp_insert(unsigned long long& best,
                                            unsigned& thrBits,
                                            unsigned long long e,
                                            int lane) {
    unsigned bal = __ballot_sync(FULLMASK, best > e);   // contiguous suffix
    if (bal) {
        int p = __ffs(bal) - 1;
        unsigned long long up = __shfl_up_sync(FULLMASK, best, 1);
        if (lane >= p) best = (lane == p) ? e : up;
    }
    thrBits = (unsigned)(__shfl_sync(FULLMASK, best, 31) >> 32);
}

__device__ __forceinline__ void process_cand(unsigned u, int pidx,
                                             unsigned long long& best,
                                             unsigned& thrBits,
                                             int lane) {
    unsigned q = __ballot_sync(FULLMASK, u <= thrBits);
    if (!q) return;
    unsigned long long k = ((unsigned long long)u << 32) | (unsigned)pidx;
    do {
        int src = __ffs(q) - 1;
        unsigned long long e = __shfl_sync(FULLMASK, k, src);
        warp_insert(best, thrBits, e, lane);
        q &= q - 1;
        q &= __ballot_sync(FULLMASK, u <= thrBits);
    } while (q);
}

__global__ __launch_bounds__(KNN_THREADS, 1)
void knn_kernel(const float* __restrict__ new_xyz) {
    extern __shared__ float4 shp[];          // 8192 x float4 = 128KB
    const int blocks_per_batch = NQUERY / QPB;   // 64
    const int b    = blockIdx.x / blocks_per_batch;
    const int qblk = blockIdx.x % blocks_per_batch;

    const float4* src = g_pts4 + (size_t)b * NPTS;
    for (int i = threadIdx.x; i < NPTS; i += KNN_THREADS) shp[i] = src[i];
    __syncthreads();

    const int w    = threadIdx.x >> 5;
    const int lane = threadIdx.x & 31;
    const int q    = qblk * QPB + w;

    const float* nq = new_xyz + ((size_t)b * NQUERY + q) * 3;
    const float qx = nq[0], qy = nq[1], qz = nq[2];

    // binary search: first sorted pos with x >= qx (all lanes redundantly)
    int lo = 0, hi = NPTS;
    while (lo < hi) {
        int mid = (lo + hi) >> 1;
        if (shp[mid].x < qx) lo = mid + 1; else hi = mid;
    }

    unsigned long long best = ~0ULL;   // sorted ascending across lanes
    unsigned thrBits = 0xffffffffu;    // dist bits of best[31] (NaN early)

    int rpos = lo, lpos = lo - 1;
    bool rdone = (rpos >= NPTS), ldone = (lpos < 0);

    while (true) {
        float thrF = __uint_as_float(thrBits);     // NaN until 32 inserted
        float rdx = 3.0e38f, ldx = 3.0e38f;
        if (!rdone) {
            rdx = shp[rpos].x - qx;                // >= 0 by search
            if (__fmul_rn(__fmul_rn(rdx, rdx), STOP_MARGIN) > thrF) rdone = true;
        }
        if (!ldone) {
            ldx = qx - shp[lpos].x;                // >= 0
            if (__fmul_rn(__fmul_rn(ldx, ldx), STOP_MARGIN) > thrF) ldone = true;
        }
        if (rdone && ldone) break;

        bool goRight = !rdone && (ldone || rdx <= ldx);
        int pos = goRight ? (rpos + lane) : (lpos - lane);
        bool ok = goRight ? (pos < NPTS) : (pos >= 0);

        unsigned u = 0xffffffffu;
        int pidx = 0x7fffffff;
        if (ok) {
            float4 p = shp[pos];
            u = __float_as_uint(sqdist(qx, qy, qz, p.x, p.y, p.z));
            pidx = __float_as_int(p.w);
        }
        process_cand(u, pidx, best, thrBits, lane);

        if (goRight) { rpos += 32; if (rpos >= NPTS) rdone = true; }
        else         { lpos -= 32; if (lpos < 0)     ldone = true; }
    }

    // lane s holds the s-th nearest neighbor (stable order)
    g_knn_idx[((size_t)b * NQUERY + q) * NS + lane] =
        (int)(unsigned)(best & 0xffffffffu);
}

// -------------------------------------------------------------- gather ----
constexpr int OUT_CH = 3 + NCH;                // 67
constexpr int ELEMS  = NQUERY * NS;            // 65536 per (b, ch)
constexpr int GATHER_THREADS = 1024;
constexpr int GSPLIT = 2;                      // blocks per (b, ch)

__global__ __launch_bounds__(GATHER_THREADS)
void gather_kernel(const float* __restrict__ xyz,
                   const float* __restrict__ new_xyz,
                   const float* __restrict__ feats,
                   float* __restrict__ out) {
    __shared__ float row[NPTS];
    __shared__ float qrow[NQUERY];
    const int bc   = blockIdx.x / GSPLIT;
    const int half = blockIdx.x % GSPLIT;
    const int b  = bc / OUT_CH;
    const int ch = bc % OUT_CH;

    if (ch >= 3) {
        const float4* src = reinterpret_cast<const float4*>(
            feats + ((size_t)b * NCH + (ch - 3)) * NPTS);
        float4* dst = reinterpret_cast<float4*>(row);
        for (int i = threadIdx.x; i < NPTS / 4; i += GATHER_THREADS) dst[i] = src[i];
    } else {
        const float* src = xyz + (size_t)b * NPTS * 3;
        for (int i = threadIdx.x; i < NPTS; i += GATHER_THREADS)
            row[i] = src[i * 3 + ch];
        const float* qsrc = new_xyz + (size_t)b * NQUERY * 3;
        for (int i = threadIdx.x; i < NQUERY; i += GATHER_THREADS)
            qrow[i] = qsrc[i * 3 + ch];
    }
    __syncthreads();

    const int4* idx4 = reinterpret_cast<const int4*>(g_knn_idx + (size_t)b * ELEMS);
    float4* ob4 = reinterpret_cast<float4*>(out + ((size_t)b * OUT_CH + ch) * ELEMS);

    constexpr int NV = ELEMS / 4;              // 16384 float4 per (b, ch)
    constexpr int NVH = NV / GSPLIT;           // per block
    const int e0 = half * NVH;

    if (ch >= 3) {
        #pragma unroll 4
        for (int e = e0 + threadIdx.x; e < e0 + NVH; e += GATHER_THREADS) {
            int4 n = idx4[e];
            ob4[e] = make_float4(row[n.x], row[n.y], row[n.z], row[n.w]);
        }
    } else {
        #pragma unroll 4
        for (int e = e0 + threadIdx.x; e < e0 + NVH; e += GATHER_THREADS) {
            int4 n = idx4[e];
            float qv = qrow[e >> 3];           // query index = (4e)/32
            float4 v;
            v.x = __fsub_rn(row[n.x], qv);
            v.y = __fsub_rn(row[n.y], qv);
            v.z = __fsub_rn(row[n.z], qv);
            v.w = __fsub_rn(row[n.w], qv);
            ob4[e] = v;
        }
    }
}

// -------------------------------------------------------------- launch ----
extern "C" void kernel_launch(void* const* d_in, const int* in_sizes, int n_in,
                              void* d_out, int out_size) {
    const float* xyz      = (const float*)d_in[0];   // (4, 8192, 3) f32
    const float* new_xyz  = (const float*)d_in[1];   // (4, 2048, 3) f32
    // d_in[2], d_in[3]: components (int64) -- dead (LAMBDA = 0.5)
    const float* feats    = (const float*)d_in[4];   // (4, 64, 8192) f32
    float* out = (float*)d_out;                      // (4, 67, 2048, 32) f32

    const int sort_smem = NPTS * sizeof(unsigned long long);   // 64KB
    const int knn_smem  = NPTS * sizeof(float4);               // 128KB
    cudaFuncSetAttribute(sort_kernel, cudaFuncAttributeMaxDynamicSharedMemorySize,
                         sort_smem);
    cudaFuncSetAttribute(knn_kernel, cudaFuncAttributeMaxDynamicSharedMemorySize,
                         knn_smem);

    sort_kernel<<<BATCH, 1024, sort_smem>>>(xyz);
    knn_kernel<<<BATCH * (NQUERY / QPB), KNN_THREADS, knn_smem>>>(new_xyz);
    gather_kernel<<<BATCH * OUT_CH * GSPLIT, GATHER_THREADS>>>(xyz, new_xyz,
                                                               feats, out);
}

// round 4
// speedup vs baseline: 1.5283x; 1.5283x over previous
#include <cuda_runtime.h>
#include <cstdint>

// GAGKNNQueryAndGroup on GB300.
// LAMBDA = 0.5 -> lam == 1-lam: the component rescale scales every distance
// by 0.5 uniformly => ordering is plain squared-distance KNN; components dead.
//
// R4 (after R3's pruning regression): back to the R2 warp-per-query brute
// scan (high ILP, regular control flow), but inserts are now BATCHED:
//  - candidates passing the (lazy) threshold are claimed into one register
//    slot per lane via ballot + __fns + shfl (no smem),
//  - every 32 accumulated candidates: warp bitonic sort-32 (15 shfl-xor
//    stages) + half-cleaner merge with the sorted best list (6 stages).
//  ~9 merges/query instead of ~210 serialized single-element inserts.
// Exactness: final best-32 = the 32 smallest 64-bit (dist_bits<<32|idx) keys,
// independent of processing order; ties resolve by index = stable argsort.

#define FULLMASK 0xffffffffu

constexpr int BATCH  = 4;
constexpr int NPTS   = 8192;
constexpr int NQUERY = 2048;
constexpr int NCH    = 64;
constexpr int NS     = 32;
constexpr int QPB    = 16;                // queries (warps) per knn block
constexpr int KNN_THREADS = QPB * 32;     // 512
constexpr int PPL    = 8;                 // points per lane per chunk
constexpr int CHUNK  = 32 * PPL;          // 256

__device__ int g_knn_idx[BATCH * NQUERY * NS];

// ------------------------------------------------------------ knn utils ----
__device__ __forceinline__ float sqdist(float qx, float qy, float qz,
                                        float x, float y, float z) {
    // No FMA contraction: elementwise mul then left-to-right add, matching
    // the reference's (diff*diff) + sum-over-3 bit-exactly.
    float dx = qx - x, dy = qy - y, dz = qz - z;
    return __fadd_rn(__fadd_rn(__fmul_rn(dx, dx), __fmul_rn(dy, dy)),
                     __fmul_rn(dz, dz));
}

// Warp bitonic sort of one 64-bit key per lane, ascending by lane id.
__device__ __forceinline__ void warp_sort32(unsigned long long& v, int lane) {
    #pragma unroll
    for (int k = 2; k <= 32; k <<= 1) {
        #pragma unroll
        for (int j = k >> 1; j > 0; j >>= 1) {
            unsigned long long o = __shfl_xor_sync(FULLMASK, v, j);
            bool keepMin = (((lane & k) == 0) == ((lane & j) == 0));
            bool less = v < o;
            v = (less == keepMin) ? v : o;
        }
    }
}

// Merge sorted best (asc) with sorted batch p (asc); keep 32 smallest, asc.
__device__ __forceinline__ void warp_merge(unsigned long long& best,
                                           unsigned long long p, int lane) {
    unsigned long long bo = __shfl_sync(FULLMASK, p, 31 - lane); // descending
    unsigned long long v = (best < bo) ? best : bo;              // half-cleaner
    #pragma unroll
    for (int j = 16; j > 0; j >>= 1) {                           // bitonic clean
        unsigned long long o = __shfl_xor_sync(FULLMASK, v, j);
        bool lower = (lane & j) == 0;
        bool less = v < o;
        v = (less == lower) ? v : o;
    }
    best = v;
}

// Enqueue candidates (lanes set in m hold key k) into per-lane pending slot;
// merge into best when 32 accumulate. All control flow warp-uniform.
__device__ __forceinline__ void enqueue(unsigned m, unsigned long long k,
                                        unsigned long long& pend, int& pcnt,
                                        unsigned long long& best,
                                        unsigned& thrBits, int lane) {
    const int cnt = __popc(m);
    int r = lane - pcnt;                       // rank this lane would consume
    int rr = min(max(r, 0), 31);
    int src = __fns(m, 0, rr + 1);             // rr-th set bit of m
    unsigned long long kk = __shfl_sync(FULLMASK, k, src & 31);
    if (r >= 0 && r < cnt) pend = kk;          // fill slots pcnt..min(pcnt+cnt,32)-1
    int pold = pcnt;
    pcnt += cnt;
    if (pcnt >= 32) {
        warp_sort32(pend, lane);
        warp_merge(best, pend, lane);
        thrBits = (unsigned)(__shfl_sync(FULLMASK, best, 31) >> 32);
        int rem = pcnt - 32;                   // <= 31 (pold<=31, cnt<=32)
        if (rem > 0) {                         // leftovers -> slots 0..rem-1
            int avail = 32 - pold;
            int r2 = min(lane + avail, 31);
            int s2 = __fns(m, 0, r2 + 1);
            unsigned long long k2 = __shfl_sync(FULLMASK, k, s2 & 31);
            if (lane < rem) pend = k2;
        }
        pcnt = rem;
    }
}

// ----------------------------------------------------------------- knn ----
__global__ __launch_bounds__(KNN_THREADS, 2)
void knn_kernel(const float* __restrict__ xyz,
                const float* __restrict__ new_xyz) {
    extern __shared__ float sh[];
    float* shx = sh;
    float* shy = sh + NPTS;
    float* shz = sh + 2 * NPTS;

    const int blocks_per_batch = NQUERY / QPB;
    const int b    = blockIdx.x / blocks_per_batch;
    const int qblk = blockIdx.x % blocks_per_batch;

    // Stage this batch's points into SoA smem (coalesced float4 reads).
    const float4* p4 = reinterpret_cast<const float4*>(xyz + (size_t)b * NPTS * 3);
    for (int j = threadIdx.x; j < NPTS * 3 / 4; j += KNN_THREADS) {
        float4 f = p4[j];
        float v[4] = {f.x, f.y, f.z, f.w};
        int flat = 4 * j;
        #pragma unroll
        for (int t = 0; t < 4; t++) {
            int p = (flat + t) / 3;
            int c = (flat + t) - 3 * p;
            float* dst = (c == 0) ? shx : (c == 1) ? shy : shz;
            dst[p] = v[t];
        }
    }
    __syncthreads();

    const int w    = threadIdx.x >> 5;
    const int lane = threadIdx.x & 31;
    const int q    = qblk * QPB + w;

    const float* nq = new_xyz + ((size_t)b * NQUERY + q) * 3;
    const float qx = nq[0], qy = nq[1], qz = nq[2];

    unsigned long long best = ~0ULL;   // sorted ascending across lanes
    unsigned long long pend = ~0ULL;   // pending batch (one slot per lane)
    unsigned thrBits = 0xffffffffu;    // dist bits of best[31] (lazy)
    int pcnt = 0;

    for (int base = 0; base < NPTS; base += CHUNK) {
        const int i0 = base + lane * PPL;   // 32B/lane: conflict-free LDS.128
        float4 X0 = *reinterpret_cast<const float4*>(shx + i0);
        float4 X1 = *reinterpret_cast<const float4*>(shx + i0 + 4);
        float4 Y0 = *reinterpret_cast<const float4*>(shy + i0);
        float4 Y1 = *reinterpret_cast<const float4*>(shy + i0 + 4);
        float4 Z0 = *reinterpret_cast<const float4*>(shz + i0);
        float4 Z1 = *reinterpret_cast<const float4*>(shz + i0 + 4);

        unsigned u[PPL];
        u[0] = __float_as_uint(sqdist(qx, qy, qz, X0.x, Y0.x, Z0.x));
        u[1] = __float_as_uint(sqdist(qx, qy, qz, X0.y, Y0.y, Z0.y));
        u[2] = __float_as_uint(sqdist(qx, qy, qz, X0.z, Y0.z, Z0.z));
        u[3] = __float_as_uint(sqdist(qx, qy, qz, X0.w, Y0.w, Z0.w));
        u[4] = __float_as_uint(sqdist(qx, qy, qz, X1.x, Y1.x, Z1.x));
        u[5] = __float_as_uint(sqdist(qx, qy, qz, X1.y, Y1.y, Z1.y));
        u[6] = __float_as_uint(sqdist(qx, qy, qz, X1.z, Y1.z, Z1.z));
        u[7] = __float_as_uint(sqdist(qx, qy, qz, X1.w, Y1.w, Z1.w));

        // min-tree (ALU pipe) then one ballot for the chunk-skip test
        unsigned mn01 = min(u[0], u[1]), mn23 = min(u[2], u[3]);
        unsigned mn45 = min(u[4], u[5]), mn67 = min(u[6], u[7]);
        unsigned mn = min(min(mn01, mn23), min(mn45, mn67));
        if (!__ballot_sync(FULLMASK, mn <= thrBits)) continue;

        #pragma unroll
        for (int t = 0; t < PPL; t++) {
            unsigned m = __ballot_sync(FULLMASK, u[t] <= thrBits);
            if (m) {
                unsigned long long k =
                    ((unsigned long long)u[t] << 32) | (unsigned)(i0 + t);
                enqueue(m, k, pend, pcnt, best, thrBits, lane);
            }
        }
    }

    // flush remaining pending candidates
    if (pcnt > 0) {
        if (lane >= pcnt) pend = ~0ULL;
        warp_sort32(pend, lane);
        warp_merge(best, pend, lane);
    }

    // lane s holds the s-th nearest neighbor (stable order)
    g_knn_idx[((size_t)b * NQUERY + q) * NS + lane] =
        (int)(unsigned)(best & 0xffffffffu);
}

// -------------------------------------------------------------- gather ----
constexpr int OUT_CH = 3 + NCH;                // 67
constexpr int ELEMS  = NQUERY * NS;            // 65536 per (b, ch)
constexpr int GATHER_THREADS = 1024;
constexpr int GSPLIT = 2;                      // blocks per (b, ch)

__global__ __launch_bounds__(GATHER_THREADS)
void gather_kernel(const float* __restrict__ xyz,
                   const float* __restrict__ new_xyz,
                   const float* __restrict__ feats,
                   float* __restrict__ out) {
    __shared__ float row[NPTS];
    __shared__ float qrow[NQUERY];
    const int bc   = blockIdx.x / GSPLIT;
    const int half = blockIdx.x % GSPLIT;
    const int b  = bc / OUT_CH;
    const int ch = bc % OUT_CH;

    if (ch >= 3) {
        const float4* src = reinterpret_cast<const float4*>(
            feats + ((size_t)b * NCH + (ch - 3)) * NPTS);
        float4* dst = reinterpret_cast<float4*>(row);
        for (int i = threadIdx.x; i < NPTS / 4; i += GATHER_THREADS) dst[i] = src[i];
    } else {
        const float* src = xyz + (size_t)b * NPTS * 3;
        for (int i = threadIdx.x; i < NPTS; i += GATHER_THREADS)
            row[i] = src[i * 3 + ch];
        const float* qsrc = new_xyz + (size_t)b * NQUERY * 3;
        for (int i = threadIdx.x; i < NQUERY; i += GATHER_THREADS)
            qrow[i] = qsrc[i * 3 + ch];
    }
    __syncthreads();

    const int4* idx4 = reinterpret_cast<const int4*>(g_knn_idx + (size_t)b * ELEMS);
    float4* ob4 = reinterpret_cast<float4*>(out + ((size_t)b * OUT_CH + ch) * ELEMS);

    constexpr int NV  = ELEMS / 4;             // 16384 float4 per (b, ch)
    constexpr int NVH = NV / GSPLIT;           // 8192 per block
    const int e0 = half * NVH;

    if (ch >= 3) {
        #pragma unroll
        for (int it = 0; it < NVH / GATHER_THREADS; it++) {
            int e = e0 + it * GATHER_THREADS + threadIdx.x;
            int4 n = idx4[e];
            ob4[e] = make_float4(row[n.x], row[n.y], row[n.z], row[n.w]);
        }
    } else {
        #pragma unroll
        for (int it = 0; it < NVH / GATHER_THREADS; it++) {
            int e = e0 + it * GATHER_THREADS + threadIdx.x;
            int4 n = idx4[e];
            float qv = qrow[e >> 3];           // query index = (4e)/32
            float4 v;
            v.x = __fsub_rn(row[n.x], qv);
            v.y = __fsub_rn(row[n.y], qv);
            v.z = __fsub_rn(row[n.z], qv);
            v.w = __fsub_rn(row[n.w], qv);
            ob4[e] = v;
        }
    }
}

// -------------------------------------------------------------- launch ----
extern "C" void kernel_launch(void* const* d_in, const int* in_sizes, int n_in,
                              void* d_out, int out_size) {
    const float* xyz      = (const float*)d_in[0];   // (4, 8192, 3) f32
    const float* new_xyz  = (const float*)d_in[1];   // (4, 2048, 3) f32
    // d_in[2], d_in[3]: components (int64) -- dead (LAMBDA = 0.5)
    const float* feats    = (const float*)d_in[4];   // (4, 64, 8192) f32
    float* out = (float*)d_out;                      // (4, 67, 2048, 32) f32

    const int knn_smem = 3 * NPTS * sizeof(float);   // 96 KB
    cudaFuncSetAttribute(knn_kernel, cudaFuncAttributeMaxDynamicSharedMemorySize,
                         knn_smem);

    knn_kernel<<<BATCH * (NQUERY / QPB), KNN_THREADS, knn_smem>>>(xyz, new_xyz);
    gather_kernel<<<BATCH * OUT_CH * GSPLIT, GATHER_THREADS>>>(xyz, new_xyz,
                                                               feats, out);
}

// round 5
// speedup vs baseline: 1.7381x; 1.1373x over previous
#include <cuda_runtime.h>
#include <cstdint>

// GAGKNNQueryAndGroup on GB300.
// LAMBDA = 0.5 -> lam == 1-lam: rescale scales every distance by 0.5 uniformly,
// ordering is plain squared-distance KNN; components inputs dead.
//
// R5: counting-sort points into 256 x-bins (prep kernel, grid=4, cheap), then
// the R2 warp-per-query scan visits 128-point chunks in two-pointer order from
// the query's bin outward, stopping a side when the chunk's exact x-bound
// guarantees every point is strictly farther than the current 32nd best
// (margin 0.9999 >> fp rounding => skipped points can't even tie). Insert path
// is R2's proven per-candidate ballot loop (R4's batched merge regressed).
// Exactness: distances computed identically to the reference (no FMA), top-32
// kept as the 32 smallest 64-bit (dist_bits<<32|orig_idx) keys -> processing-
// order invariant, ties by index == stable argsort.

#define FULLMASK 0xffffffffu

constexpr int BATCH  = 4;
constexpr int NPTS   = 8192;
constexpr int NQUERY = 2048;
constexpr int NCH    = 64;
constexpr int NS     = 32;
constexpr int NBINS  = 256;
constexpr int NCHK   = NPTS / 128;        // 64 chunks per batch
constexpr int QPB    = 16;                // queries (warps) per knn block
constexpr int KNN_THREADS = QPB * 32;     // 512
constexpr float STOP = 0.9999f;           // conservative prune margin

__device__ float g_bx[BATCH * NPTS];
__device__ float g_by[BATCH * NPTS];
__device__ float g_bz[BATCH * NPTS];
__device__ __align__(16) unsigned short g_bidx[BATCH * NPTS];
__device__ unsigned g_cminE[BATCH * NCHK];
__device__ unsigned g_cmaxE[BATCH * NCHK];
__device__ int g_binstart[BATCH * NBINS];
__device__ int g_knn_idx[BATCH * NQUERY * NS];

__device__ __forceinline__ int binof(float x) {
    int b = (int)((x + 4.5f) * (NBINS / 9.0f));
    return min(max(b, 0), NBINS - 1);
}
// order-preserving float <-> unsigned encode (for atomicMin/Max)
__device__ __forceinline__ unsigned encf(float x) {
    unsigned u = __float_as_uint(x);
    return (u & 0x80000000u) ? ~u : (u | 0x80000000u);
}
__device__ __forceinline__ float decf(unsigned e) {
    unsigned u = (e & 0x80000000u) ? (e ^ 0x80000000u) : ~e;
    return __uint_as_float(u);
}

// ---------------------------------------------------------------- prep ----
__global__ void prep_kernel(const float* __restrict__ xyz) {
    __shared__ unsigned hist[NBINS];
    __shared__ int bstart[NBINS];
    __shared__ unsigned cmnE[NCHK], cmxE[NCHK];
    const int b = blockIdx.x;
    const int tid = threadIdx.x;
    const int bd = blockDim.x;

    for (int i = tid; i < NBINS; i += bd) hist[i] = 0;
    for (int i = tid; i < NCHK; i += bd) { cmnE[i] = 0xffffffffu; cmxE[i] = 0u; }
    __syncthreads();

    for (int i = tid; i < NPTS; i += bd) {
        float x = xyz[((size_t)b * NPTS + i) * 3];
        atomicAdd(&hist[binof(x)], 1u);
    }
    __syncthreads();

    if (tid < 32) {   // exclusive prefix over 256 bins, one warp
        int lane = tid;
        unsigned v[8], pre[8], run = 0;
        #pragma unroll
        for (int k = 0; k < 8; k++) { v[k] = hist[lane * 8 + k]; pre[k] = run; run += v[k]; }
        unsigned tot = run;
        #pragma unroll
        for (int off = 1; off < 32; off <<= 1) {
            unsigned t = __shfl_up_sync(FULLMASK, run, off);
            if (lane >= off) run += t;
        }
        unsigned excl = run - tot;
        #pragma unroll
        for (int k = 0; k < 8; k++) bstart[lane * 8 + k] = (int)(excl + pre[k]);
    }
    __syncthreads();

    for (int i = tid; i < NBINS; i += bd) hist[i] = 0;   // reuse as cursors
    __syncthreads();

    for (int i = tid; i < NPTS; i += bd) {
        const float* p = xyz + ((size_t)b * NPTS + i) * 3;
        float x = p[0], y = p[1], z = p[2];
        int bin = binof(x);
        int pos = bstart[bin] + (int)atomicAdd(&hist[bin], 1u);
        size_t o = (size_t)b * NPTS + pos;
        g_bx[o] = x; g_by[o] = y; g_bz[o] = z;
        g_bidx[o] = (unsigned short)i;
        int c = pos >> 7;
        unsigned e = encf(x);
        atomicMin(&cmnE[c], e);
        atomicMax(&cmxE[c], e);
    }
    __syncthreads();

    for (int i = tid; i < NCHK; i += bd) {
        g_cminE[b * NCHK + i] = cmnE[i];
        g_cmaxE[b * NCHK + i] = cmxE[i];
    }
    for (int i = tid; i < NBINS; i += bd) g_binstart[b * NBINS + i] = bstart[i];
}

// ------------------------------------------------------------ knn utils ----
__device__ __forceinline__ float sqdist(float qx, float qy, float qz,
                                        float x, float y, float z) {
    // No FMA contraction: matches reference (diff*diff then sum) bit-exactly.
    float dx = qx - x, dy = qy - y, dz = qz - z;
    return __fadd_rn(__fadd_rn(__fmul_rn(dx, dx), __fmul_rn(dy, dy)),
                     __fmul_rn(dz, dz));
}

__device__ __forceinline__ void warp_insert(unsigned long long& best,
                                            unsigned& thrBits,
                                            unsigned long long e,
                                            int lane) {
    unsigned bal = __ballot_sync(FULLMASK, best > e);   // contiguous suffix
    if (bal) {
        int p = __ffs(bal) - 1;
        unsigned long long up = __shfl_up_sync(FULLMASK, best, 1);
        if (lane >= p) best = (lane == p) ? e : up;
    }
    thrBits = (unsigned)(__shfl_sync(FULLMASK, best, 31) >> 32);
}

__device__ __forceinline__ void process_cand(unsigned u, int pidx,
                                             unsigned long long& best,
                                             unsigned& thrBits,
                                             int lane) {
    unsigned q = __ballot_sync(FULLMASK, u <= thrBits);
    if (!q) return;
    unsigned long long k = ((unsigned long long)u << 32) | (unsigned)pidx;
    do {
        int src = __ffs(q) - 1;
        unsigned long long e = __shfl_sync(FULLMASK, k, src);
        warp_insert(best, thrBits, e, lane);
        q &= q - 1;
        q &= __ballot_sync(FULLMASK, u <= thrBits);
    } while (q);
}

// ----------------------------------------------------------------- knn ----
// smem layout (bytes): x[8192]f @0, y @32768, z @65536, idx u16 @98304,
// cmin f[64] @114688, cmax f[64] @114944; total 115200 (112.5 KB)
constexpr int SH_X = 0, SH_Y = 32768, SH_Z = 65536, SH_I = 98304;
constexpr int SH_CMIN = 114688, SH_CMAX = 114944, SH_TOTAL = 115200;

__global__ __launch_bounds__(KNN_THREADS, 2)
void knn_kernel(const float* __restrict__ new_xyz) {
    extern __shared__ char sh[];
    float* shx = (float*)(sh + SH_X);
    float* shy = (float*)(sh + SH_Y);
    float* shz = (float*)(sh + SH_Z);
    unsigned short* sidx = (unsigned short*)(sh + SH_I);
    float* scmin = (float*)(sh + SH_CMIN);
    float* scmax = (float*)(sh + SH_CMAX);

    const int blocks_per_batch = NQUERY / QPB;   // 128
    const int b    = blockIdx.x / blocks_per_batch;
    const int qblk = blockIdx.x % blocks_per_batch;

    {   // stage binned SoA points + u16 indices + chunk bounds
        const float4* px = (const float4*)(g_bx + (size_t)b * NPTS);
        const float4* py = (const float4*)(g_by + (size_t)b * NPTS);
        const float4* pz = (const float4*)(g_bz + (size_t)b * NPTS);
        for (int i = threadIdx.x; i < NPTS / 4; i += KNN_THREADS) {
            ((float4*)shx)[i] = px[i];
            ((float4*)shy)[i] = py[i];
            ((float4*)shz)[i] = pz[i];
        }
        const uint4* pi = (const uint4*)(g_bidx + (size_t)b * NPTS);
        for (int i = threadIdx.x; i < NPTS * 2 / 16; i += KNN_THREADS)
            ((uint4*)sidx)[i] = pi[i];
        for (int i = threadIdx.x; i < NCHK; i += KNN_THREADS) {
            scmin[i] = decf(g_cminE[b * NCHK + i]);
            scmax[i] = decf(g_cmaxE[b * NCHK + i]);
        }
    }
    __syncthreads();

    const int w    = threadIdx.x >> 5;
    const int lane = threadIdx.x & 31;
    const int q    = qblk * QPB + w;

    const float* nq = new_xyz + ((size_t)b * NQUERY + q) * 3;
    const float qx = nq[0], qy = nq[1], qz = nq[2];

    unsigned long long best = ~0ULL;   // sorted ascending across lanes
    unsigned thrBits = 0xffffffffu;    // dist bits of best[31] (NaN while <32)

    int pos0 = g_binstart[b * NBINS + binof(qx)];
    int c0 = min(pos0 >> 7, NCHK - 1);
    int rc = c0, lc = c0 - 1;
    bool rdone = false, ldone = (lc < 0);

    while (true) {
        float thrF = __uint_as_float(thrBits);   // NaN until 32 found -> no prune
        float rb = 0.0f, lb = 0.0f;
        if (!rdone) {
            rb = fmaxf(__fsub_rn(scmin[rc], qx), 0.0f);
            if (__fmul_rn(__fmul_rn(rb, rb), STOP) > thrF) rdone = true;
        }
        if (!ldone) {
            lb = fmaxf(__fsub_rn(qx, scmax[lc]), 0.0f);
            if (__fmul_rn(__fmul_rn(lb, lb), STOP) > thrF) ldone = true;
        }
        if (rdone && ldone) break;

        bool goRight = !rdone && (ldone || rb <= lb);
        int c;
        if (goRight) { c = rc++; if (rc >= NCHK) rdone = true; }
        else         { c = lc--; if (lc < 0)     ldone = true; }

        const int i0 = c * 128 + lane * 4;   // 16B/lane: conflict-free LDS.128
        float4 X = *reinterpret_cast<const float4*>(shx + i0);
        float4 Y = *reinterpret_cast<const float4*>(shy + i0);
        float4 Z = *reinterpret_cast<const float4*>(shz + i0);

        unsigned u0 = __float_as_uint(sqdist(qx, qy, qz, X.x, Y.x, Z.x));
        unsigned u1 = __float_as_uint(sqdist(qx, qy, qz, X.y, Y.y, Z.y));
        unsigned u2 = __float_as_uint(sqdist(qx, qy, qz, X.z, Y.z, Z.z));
        unsigned u3 = __float_as_uint(sqdist(qx, qy, qz, X.w, Y.w, Z.w));

        bool any = (u0 <= thrBits) | (u1 <= thrBits) |
                   (u2 <= thrBits) | (u3 <= thrBits);
        if (__ballot_sync(FULLMASK, any)) {
            uint2 packed = *reinterpret_cast<const uint2*>(sidx + i0);
            process_cand(u0, (int)(packed.x & 0xffffu), best, thrBits, lane);
            process_cand(u1, (int)(packed.x >> 16),     best, thrBits, lane);
            process_cand(u2, (int)(packed.y & 0xffffu), best, thrBits, lane);
            process_cand(u3, (int)(packed.y >> 16),     best, thrBits, lane);
        }
    }

    // lane s holds the s-th nearest neighbor (stable order)
    g_knn_idx[((size_t)b * NQUERY + q) * NS + lane] =
        (int)(unsigned)(best & 0xffffffffu);
}

// -------------------------------------------------------------- gather ----
constexpr int OUT_CH = 3 + NCH;                // 67
constexpr int ELEMS  = NQUERY * NS;            // 65536 per (b, ch)
constexpr int GATHER_THREADS = 1024;
constexpr int GSPLIT = 2;                      // blocks per (b, ch)

__global__ __launch_bounds__(GATHER_THREADS)
void gather_kernel(const float* __restrict__ xyz,
                   const float* __restrict__ new_xyz,
                   const float* __restrict__ feats,
                   float* __restrict__ out) {
    __shared__ float row[NPTS];
    __shared__ float qrow[NQUERY];
    const int bc   = blockIdx.x / GSPLIT;
    const int half = blockIdx.x % GSPLIT;
    const int b  = bc / OUT_CH;
    const int ch = bc % OUT_CH;

    if (ch >= 3) {
        const float4* src = reinterpret_cast<const float4*>(
            feats + ((size_t)b * NCH + (ch - 3)) * NPTS);
        float4* dst = reinterpret_cast<float4*>(row);
        for (int i = threadIdx.x; i < NPTS / 4; i += GATHER_THREADS) dst[i] = src[i];
    } else {
        const float* src = xyz + (size_t)b * NPTS * 3;
        for (int i = threadIdx.x; i < NPTS; i += GATHER_THREADS)
            row[i] = src[i * 3 + ch];
        const float* qsrc = new_xyz + (size_t)b * NQUERY * 3;
        for (int i = threadIdx.x; i < NQUERY; i += GATHER_THREADS)
            qrow[i] = qsrc[i * 3 + ch];
    }
    __syncthreads();

    const int4* idx4 = reinterpret_cast<const int4*>(g_knn_idx + (size_t)b * ELEMS);
    float4* ob4 = reinterpret_cast<float4*>(out + ((size_t)b * OUT_CH + ch) * ELEMS);

    constexpr int NV  = ELEMS / 4;             // 16384 float4 per (b, ch)
    constexpr int NVH = NV / GSPLIT;           // 8192 per block
    const int e0 = half * NVH;

    if (ch >= 3) {
        #pragma unroll
        for (int it = 0; it < NVH / GATHER_THREADS; it++) {
            int e = e0 + it * GATHER_THREADS + threadIdx.x;
            int4 n = idx4[e];
            ob4[e] = make_float4(row[n.x], row[n.y], row[n.z], row[n.w]);
        }
    } else {
        #pragma unroll
        for (int it = 0; it < NVH / GATHER_THREADS; it++) {
            int e = e0 + it * GATHER_THREADS + threadIdx.x;
            int4 n = idx4[e];
            float qv = qrow[e >> 3];           // query index = (4e)/32
            float4 v;
            v.x = __fsub_rn(row[n.x], qv);
            v.y = __fsub_rn(row[n.y], qv);
            v.z = __fsub_rn(row[n.z], qv);
            v.w = __fsub_rn(row[n.w], qv);
            ob4[e] = v;
        }
    }
}

// -------------------------------------------------------------- launch ----
extern "C" void kernel_launch(void* const* d_in, const int* in_sizes, int n_in,
                              void* d_out, int out_size) {
    const float* xyz      = (const float*)d_in[0];   // (4, 8192, 3) f32
    const float* new_xyz  = (const float*)d_in[1];   // (4, 2048, 3) f32
    // d_in[2], d_in[3]: components (int64) -- dead (LAMBDA = 0.5)
    const float* feats    = (const float*)d_in[4];   // (4, 64, 8192) f32
    float* out = (float*)d_out;                      // (4, 67, 2048, 32) f32

    cudaFuncSetAttribute(knn_kernel, cudaFuncAttributeMaxDynamicSharedMemorySize,
                         SH_TOTAL);

    prep_kernel<<<BATCH, 1024>>>(xyz);
    knn_kernel<<<BATCH * (NQUERY / QPB), KNN_THREADS, SH_TOTAL>>>(new_xyz);
    gather_kernel<<<BATCH * OUT_CH * GSPLIT, GATHER_THREADS>>>(xyz, new_xyz,
                                                               feats, out);
}

// round 6
// speedup vs baseline: 2.4265x; 1.3961x over previous
#include <cuda_runtime.h>
#include <cstdint>

// GAGKNNQueryAndGroup on GB300.
// LAMBDA = 0.5 -> lam == 1-lam: rescale scales every distance by 0.5 uniformly,
// ordering is plain squared-distance KNN; components inputs dead.
//
// R6 = R5 with the two measured hot spots fixed:
//  - prep split into 3 wide-grid kernels (hist / scan / scatter, 8 parts per
//    batch); chunk x-bounds come from bin EDGES (computed in scan; provably
//    conservative) so scatter needs no min/max atomics. 26us -> ~8us.
//  - knn bootstraps the first (local) chunk via warp bitonic sort-32 + merge
//    instead of ~128 serialized single inserts; after that thr is near-final.
// Exactness: distances computed with the reference's exact op order (no FMA);
// top-32 = 32 smallest (dist_bits<<32|orig_idx) keys -> order invariant, ties
// by index == stable argsort. Prune margin 0.9999 >> fp rounding, bin-edge
// bounds <= true chunk bounds.

#define FULLMASK 0xffffffffu

constexpr int BATCH  = 4;
constexpr int NPTS   = 8192;
constexpr int NQUERY = 2048;
constexpr int NCH    = 64;
constexpr int NS     = 32;
constexpr int NBINS  = 256;
constexpr int NCHK   = NPTS / 128;        // 64 chunks per batch
constexpr int PARTS  = 8;                 // prep blocks per batch
constexpr int PPTS   = NPTS / PARTS;      // 1024 points per prep block
constexpr int QPB    = 16;                // queries (warps) per knn block
constexpr int KNN_THREADS = QPB * 32;     // 512
constexpr float STOP = 0.9999f;           // conservative prune margin

__device__ float g_bx[BATCH * NPTS];
__device__ float g_by[BATCH * NPTS];
__device__ float g_bz[BATCH * NPTS];
__device__ __align__(16) unsigned short g_bidx[BATCH * NPTS];
__device__ unsigned g_hist_part[BATCH * PARTS * NBINS];
__device__ unsigned g_partoff[BATCH * PARTS * NBINS];
__device__ int g_binstart[BATCH * NBINS];
__device__ float g_cbmin[BATCH * NCHK];
__device__ float g_cbmax[BATCH * NCHK];
__device__ int g_knn_idx[BATCH * NQUERY * NS];

__device__ __forceinline__ int binof(float x) {
    int b = (int)((x + 4.5f) * (NBINS / 9.0f));
    return min(max(b, 0), NBINS - 1);
}

// ---------------------------------------------------------------- prep ----
__global__ void hist_kernel(const float* __restrict__ xyz) {
    __shared__ unsigned h[NBINS];
    const int b = blockIdx.x / PARTS, p = blockIdx.x % PARTS;
    const int tid = threadIdx.x;
    for (int i = tid; i < NBINS; i += 256) h[i] = 0;
    __syncthreads();
    const int base = p * PPTS;
    for (int i = tid; i < PPTS; i += 256) {
        float x = xyz[((size_t)b * NPTS + base + i) * 3];
        atomicAdd(&h[binof(x)], 1u);
    }
    __syncthreads();
    for (int i = tid; i < NBINS; i += 256)
        g_hist_part[((size_t)b * PARTS + p) * NBINS + i] = h[i];
}

__global__ void scan_kernel() {
    __shared__ unsigned wsum[8];
    __shared__ int sstart[NBINS];
    const int b = blockIdx.x;
    const int tid = threadIdx.x;          // == bin, 256 threads
    const int lane = tid & 31, wid = tid >> 5;

    unsigned v = 0;
    #pragma unroll
    for (int p = 0; p < PARTS; p++)
        v += g_hist_part[((size_t)b * PARTS + p) * NBINS + tid];

    unsigned incl = v;                    // block-wide exclusive scan
    #pragma unroll
    for (int off = 1; off < 32; off <<= 1) {
        unsigned t = __shfl_up_sync(FULLMASK, incl, off);
        if (lane >= off) incl += t;
    }
    if (lane == 31) wsum[wid] = incl;
    __syncthreads();
    if (wid == 0) {
        unsigned s = (lane < 8) ? wsum[lane] : 0, o = s;
        #pragma unroll
        for (int off = 1; off < 8; off <<= 1) {
            unsigned t = __shfl_up_sync(FULLMASK, s, off);
            if (lane >= off) s += t;
        }
        if (lane < 8) wsum[lane] = s - o;
    }
    __syncthreads();
    unsigned excl = incl - v + wsum[wid];
    sstart[tid] = (int)excl;
    g_binstart[b * NBINS + tid] = (int)excl;

    unsigned run = excl;                  // per-part cursors
    #pragma unroll
    for (int p = 0; p < PARTS; p++) {
        g_partoff[((size_t)b * PARTS + p) * NBINS + tid] = run;
        run += g_hist_part[((size_t)b * PARTS + p) * NBINS + tid];
    }
    __syncthreads();

    if (tid < NCHK) {                     // conservative chunk x-bounds
        int posL = tid * 128, posR = posL + 127;
        int lo = 0, hi = NBINS - 1;       // last bin with start <= posL
        while (lo < hi) { int m = (lo + hi + 1) >> 1;
                          if (sstart[m] <= posL) lo = m; else hi = m - 1; }
        int binL = lo;
        lo = binL; hi = NBINS - 1;        // last bin with start <= posR
        while (lo < hi) { int m = (lo + hi + 1) >> 1;
                          if (sstart[m] <= posR) lo = m; else hi = m - 1; }
        int binR = lo;
        float eL = (binL == 0) ? -1e30f
                 : binL * (9.0f / NBINS) - 4.5f - 1e-3f;
        float eR = (binR == NBINS - 1) ? 1e30f
                 : (binR + 1) * (9.0f / NBINS) - 4.5f + 1e-3f;
        g_cbmin[b * NCHK + tid] = eL;
        g_cbmax[b * NCHK + tid] = eR;
    }
}

__global__ void scatter_kernel(const float* __restrict__ xyz) {
    __shared__ unsigned cur[NBINS];
    const int b = blockIdx.x / PARTS, p = blockIdx.x % PARTS;
    const int tid = threadIdx.x;
    for (int i = tid; i < NBINS; i += 256)
        cur[i] = g_partoff[((size_t)b * PARTS + p) * NBINS + i];
    __syncthreads();
    const int base = p * PPTS;
    for (int i = tid; i < PPTS; i += 256) {
        const float* pt = xyz + ((size_t)b * NPTS + base + i) * 3;
        float x = pt[0], y = pt[1], z = pt[2];
        int pos = (int)atomicAdd(&cur[binof(x)], 1u);
        size_t o = (size_t)b * NPTS + pos;
        g_bx[o] = x; g_by[o] = y; g_bz[o] = z;
        g_bidx[o] = (unsigned short)(base + i);
    }
}

// ------------------------------------------------------------ knn utils ----
__device__ __forceinline__ float sqdist(float qx, float qy, float qz,
                                        float x, float y, float z) {
    // No FMA contraction: matches reference (diff*diff then sum) bit-exactly.
    float dx = qx - x, dy = qy - y, dz = qz - z;
    return __fadd_rn(__fadd_rn(__fmul_rn(dx, dx), __fmul_rn(dy, dy)),
                     __fmul_rn(dz, dz));
}

__device__ __forceinline__ void warp_sort32(unsigned long long& v, int lane) {
    #pragma unroll
    for (int k = 2; k <= 32; k <<= 1) {
        #pragma unroll
        for (int j = k >> 1; j > 0; j >>= 1) {
            unsigned long long o = __shfl_xor_sync(FULLMASK, v, j);
            bool keepMin = (((lane & k) == 0) == ((lane & j) == 0));
            bool less = v < o;
            v = (less == keepMin) ? v : o;
        }
    }
}

// Merge sorted best (asc) with sorted batch p (asc); keep 32 smallest, asc.
__device__ __forceinline__ void warp_merge(unsigned long long& best,
                                           unsigned long long p, int lane) {
    unsigned long long bo = __shfl_sync(FULLMASK, p, 31 - lane);
    unsigned long long v = (best < bo) ? best : bo;
    #pragma unroll
    for (int j = 16; j > 0; j >>= 1) {
        unsigned long long o = __shfl_xor_sync(FULLMASK, v, j);
        bool lower = (lane & j) == 0;
        bool less = v < o;
        v = (less == lower) ? v : o;
    }
    best = v;
}

__device__ __forceinline__ void warp_insert(unsigned long long& best,
                                            unsigned& thrBits,
                                            unsigned long long e,
                                            int lane) {
    unsigned bal = __ballot_sync(FULLMASK, best > e);
    if (bal) {
        int p = __ffs(bal) - 1;
        unsigned long long up = __shfl_up_sync(FULLMASK, best, 1);
        if (lane >= p) best = (lane == p) ? e : up;
    }
    thrBits = (unsigned)(__shfl_sync(FULLMASK, best, 31) >> 32);
}

__device__ __forceinline__ void process_cand(unsigned u, int pidx,
                                             unsigned long long& best,
                                             unsigned& thrBits,
                                             int lane) {
    unsigned q = __ballot_sync(FULLMASK, u <= thrBits);
    if (!q) return;
    unsigned long long k = ((unsigned long long)u << 32) | (unsigned)pidx;
    do {
        int src = __ffs(q) - 1;
        unsigned long long e = __shfl_sync(FULLMASK, k, src);
        warp_insert(best, thrBits, e, lane);
        q &= q - 1;
        q &= __ballot_sync(FULLMASK, u <= thrBits);
    } while (q);
}

// ----------------------------------------------------------------- knn ----
// smem bytes: x[8192]f @0, y @32768, z @65536, idx u16 @98304,
// cmin f[64] @114688, cmax f[64] @114944; total 115200 (112.5 KB)
constexpr int SH_X = 0, SH_Y = 32768, SH_Z = 65536, SH_I = 98304;
constexpr int SH_CMIN = 114688, SH_CMAX = 114944, SH_TOTAL = 115200;

__global__ __launch_bounds__(KNN_THREADS, 2)
void knn_kernel(const float* __restrict__ new_xyz) {
    extern __shared__ char sh[];
    float* shx = (float*)(sh + SH_X);
    float* shy = (float*)(sh + SH_Y);
    float* shz = (float*)(sh + SH_Z);
    unsigned short* sidx = (unsigned short*)(sh + SH_I);
    float* scmin = (float*)(sh + SH_CMIN);
    float* scmax = (float*)(sh + SH_CMAX);

    const int blocks_per_batch = NQUERY / QPB;   // 128
    const int b    = blockIdx.x / blocks_per_batch;
    const int qblk = blockIdx.x % blocks_per_batch;

    {
        const float4* px = (const float4*)(g_bx + (size_t)b * NPTS);
        const float4* py = (const float4*)(g_by + (size_t)b * NPTS);
        const float4* pz = (const float4*)(g_bz + (size_t)b * NPTS);
        for (int i = threadIdx.x; i < NPTS / 4; i += KNN_THREADS) {
            ((float4*)shx)[i] = px[i];
            ((float4*)shy)[i] = py[i];
            ((float4*)shz)[i] = pz[i];
        }
        const uint4* pi = (const uint4*)(g_bidx + (size_t)b * NPTS);
        for (int i = threadIdx.x; i < NPTS * 2 / 16; i += KNN_THREADS)
            ((uint4*)sidx)[i] = pi[i];
        for (int i = threadIdx.x; i < NCHK; i += KNN_THREADS) {
            scmin[i] = g_cbmin[b * NCHK + i];
            scmax[i] = g_cbmax[b * NCHK + i];
        }
    }
    __syncthreads();

    const int w    = threadIdx.x >> 5;
    const int lane = threadIdx.x & 31;
    const int q    = qblk * QPB + w;

    const float* nq = new_xyz + ((size_t)b * NQUERY + q) * 3;
    const float qx = nq[0], qy = nq[1], qz = nq[2];

    unsigned long long best = ~0ULL;
    unsigned thrBits;

    const int pos0 = g_binstart[b * NBINS + binof(qx)];
    const int c0 = min(pos0 >> 7, NCHK - 1);

    {   // bootstrap: full sort+merge of the query's own chunk (128 points)
        const int i0 = c0 * 128 + lane * 4;
        float4 X = *reinterpret_cast<const float4*>(shx + i0);
        float4 Y = *reinterpret_cast<const float4*>(shy + i0);
        float4 Z = *reinterpret_cast<const float4*>(shz + i0);
        uint2 pk = *reinterpret_cast<const uint2*>(sidx + i0);

        unsigned long long v;
        v = ((unsigned long long)__float_as_uint(sqdist(qx, qy, qz, X.x, Y.x, Z.x)) << 32)
            | (pk.x & 0xffffu);
        warp_sort32(v, lane); warp_merge(best, v, lane);
        v = ((unsigned long long)__float_as_uint(sqdist(qx, qy, qz, X.y, Y.y, Z.y)) << 32)
            | (pk.x >> 16);
        warp_sort32(v, lane); warp_merge(best, v, lane);
        v = ((unsigned long long)__float_as_uint(sqdist(qx, qy, qz, X.z, Y.z, Z.z)) << 32)
            | (pk.y & 0xffffu);
        warp_sort32(v, lane); warp_merge(best, v, lane);
        v = ((unsigned long long)__float_as_uint(sqdist(qx, qy, qz, X.w, Y.w, Z.w)) << 32)
            | (pk.y >> 16);
        warp_sort32(v, lane); warp_merge(best, v, lane);
        thrBits = (unsigned)(__shfl_sync(FULLMASK, best, 31) >> 32);
    }

    int rc = c0 + 1, lc = c0 - 1;
    bool rdone = (rc >= NCHK), ldone = (lc < 0);

    while (!(rdone && ldone)) {
        float thrF = __uint_as_float(thrBits);
        float rb = 0.0f, lb = 0.0f;
        if (!rdone) {
            rb = fmaxf(__fsub_rn(scmin[rc], qx), 0.0f);
            if (__fmul_rn(__fmul_rn(rb, rb), STOP) > thrF) rdone = true;
        }
        if (!ldone) {
            lb = fmaxf(__fsub_rn(qx, scmax[lc]), 0.0f);
            if (__fmul_rn(__fmul_rn(lb, lb), STOP) > thrF) ldone = true;
        }
        if (rdone && ldone) break;

        bool goRight = !rdone && (ldone || rb <= lb);
        int c;
        if (goRight) { c = rc++; if (rc >= NCHK) rdone = true; }
        else         { c = lc--; if (lc < 0)     ldone = true; }

        const int i0 = c * 128 + lane * 4;
        float4 X = *reinterpret_cast<const float4*>(shx + i0);
        float4 Y = *reinterpret_cast<const float4*>(shy + i0);
        float4 Z = *reinterpret_cast<const float4*>(shz + i0);

        unsigned u0 = __float_as_uint(sqdist(qx, qy, qz, X.x, Y.x, Z.x));
        unsigned u1 = __float_as_uint(sqdist(qx, qy, qz, X.y, Y.y, Z.y));
        unsigned u2 = __float_as_uint(sqdist(qx, qy, qz, X.z, Y.z, Z.z));
        unsigned u3 = __float_as_uint(sqdist(qx, qy, qz, X.w, Y.w, Z.w));

        bool any = (u0 <= thrBits) | (u1 <= thrBits) |
                   (u2 <= thrBits) | (u3 <= thrBits);
        if (__ballot_sync(FULLMASK, any)) {
            uint2 pk = *reinterpret_cast<const uint2*>(sidx + i0);
            process_cand(u0, (int)(pk.x & 0xffffu), best, thrBits, lane);
            process_cand(u1, (int)(pk.x >> 16),     best, thrBits, lane);
            process_cand(u2, (int)(pk.y & 0xffffu), best, thrBits, lane);
            process_cand(u3, (int)(pk.y >> 16),     best, thrBits, lane);
        }
    }

    g_knn_idx[((size_t)b * NQUERY + q) * NS + lane] =
        (int)(unsigned)(best & 0xffffffffu);
}

// -------------------------------------------------------------- gather ----
constexpr int OUT_CH = 3 + NCH;                // 67
constexpr int ELEMS  = NQUERY * NS;            // 65536 per (b, ch)
constexpr int GATHER_THREADS = 1024;
constexpr int GSPLIT = 2;

__global__ __launch_bounds__(GATHER_THREADS)
void gather_kernel(const float* __restrict__ xyz,
                   const float* __restrict__ new_xyz,
                   const float* __restrict__ feats,
                   float* __restrict__ out) {
    __shared__ float row[NPTS];
    __shared__ float qrow[NQUERY];
    const int bc   = blockIdx.x / GSPLIT;
    const int half = blockIdx.x % GSPLIT;
    const int b  = bc / OUT_CH;
    const int ch = bc % OUT_CH;

    if (ch >= 3) {
        const float4* src = reinterpret_cast<const float4*>(
            feats + ((size_t)b * NCH + (ch - 3)) * NPTS);
        float4* dst = reinterpret_cast<float4*>(row);
        for (int i = threadIdx.x; i < NPTS / 4; i += GATHER_THREADS) dst[i] = src[i];
    } else {
        const float* src = xyz + (size_t)b * NPTS * 3;
        for (int i = threadIdx.x; i < NPTS; i += GATHER_THREADS)
            row[i] = src[i * 3 + ch];
        const float* qsrc = new_xyz + (size_t)b * NQUERY * 3;
        for (int i = threadIdx.x; i < NQUERY; i += GATHER_THREADS)
            qrow[i] = qsrc[i * 3 + ch];
    }
    __syncthreads();

    const int4* idx4 = reinterpret_cast<const int4*>(g_knn_idx + (size_t)b * ELEMS);
    float4* ob4 = reinterpret_cast<float4*>(out + ((size_t)b * OUT_CH + ch) * ELEMS);

    constexpr int NV  = ELEMS / 4;
    constexpr int NVH = NV / GSPLIT;
    const int e0 = half * NVH;

    if (ch >= 3) {
        #pragma unroll
        for (int it = 0; it < NVH / GATHER_THREADS; it++) {
            int e = e0 + it * GATHER_THREADS + threadIdx.x;
            int4 n = idx4[e];
            ob4[e] = make_float4(row[n.x], row[n.y], row[n.z], row[n.w]);
        }
    } else {
        #pragma unroll
        for (int it = 0; it < NVH / GATHER_THREADS; it++) {
            int e = e0 + it * GATHER_THREADS + threadIdx.x;
            int4 n = idx4[e];
            float qv = qrow[e >> 3];
            float4 v;
            v.x = __fsub_rn(row[n.x], qv);
            v.y = __fsub_rn(row[n.y], qv);
            v.z = __fsub_rn(row[n.z], qv);
            v.w = __fsub_rn(row[n.w], qv);
            ob4[e] = v;
        }
    }
}

// -------------------------------------------------------------- launch ----
extern "C" void kernel_launch(void* const* d_in, const int* in_sizes, int n_in,
                              void* d_out, int out_size) {
    const float* xyz      = (const float*)d_in[0];   // (4, 8192, 3) f32
    const float* new_xyz  = (const float*)d_in[1];   // (4, 2048, 3) f32
    // d_in[2], d_in[3]: components (int64) -- dead (LAMBDA = 0.5)
    const float* feats    = (const float*)d_in[4];   // (4, 64, 8192) f32
    float* out = (float*)d_out;                      // (4, 67, 2048, 32) f32

    cudaFuncSetAttribute(knn_kernel, cudaFuncAttributeMaxDynamicSharedMemorySize,
                         SH_TOTAL);

    hist_kernel<<<BATCH * PARTS, 256>>>(xyz);
    scan_kernel<<<BATCH, 256>>>();
    scatter_kernel<<<BATCH * PARTS, 256>>>(xyz);
    knn_kernel<<<BATCH * (NQUERY / QPB), KNN_THREADS, SH_TOTAL>>>(new_xyz);
    gather_kernel<<<BATCH * OUT_CH * GSPLIT, GATHER_THREADS>>>(xyz, new_xyz,
                                                               feats, out);
}

// round 7
// speedup vs baseline: 2.4358x; 1.0038x over previous
#include <cuda_runtime.h>
#include <cstdint>

// GAGKNNQueryAndGroup on GB300.
// LAMBDA = 0.5 -> lam == 1-lam: rescale scales every distance by 0.5 uniformly,
// ordering is plain squared-distance KNN; components inputs dead.
//
// R7 = R6 with the smem staging removed from knn: the binned per-batch point
// set (112.5 KB) is L1-resident, so points/indices are read via __ldg and the
// 96KB smem that capped occupancy at 2 blocks/SM is gone. 3 blocks/SM (48
// warps) now hide the serialized shuffle-insert chains. Chunk x-bounds stay in
// a 512B smem table. Gather GSPLIT 2->4 for shorter waves.
// Exactness: distances use the reference's exact op order (no FMA); top-32 =
// 32 smallest (dist_bits<<32|orig_idx) keys -> processing-order invariant,
// ties by index == stable argsort; bin-edge prune bounds are conservative.

#define FULLMASK 0xffffffffu

constexpr int BATCH  = 4;
constexpr int NPTS   = 8192;
constexpr int NQUERY = 2048;
constexpr int NCH    = 64;
constexpr int NS     = 32;
constexpr int NBINS  = 256;
constexpr int NCHK   = NPTS / 128;        // 64 chunks per batch
constexpr int PARTS  = 8;                 // prep blocks per batch
constexpr int PPTS   = NPTS / PARTS;      // 1024 points per prep block
constexpr int QPB    = 16;                // queries (warps) per knn block
constexpr int KNN_THREADS = QPB * 32;     // 512
constexpr float STOP = 0.9999f;           // conservative prune margin

__device__ float g_bx[BATCH * NPTS];
__device__ float g_by[BATCH * NPTS];
__device__ float g_bz[BATCH * NPTS];
__device__ __align__(16) unsigned short g_bidx[BATCH * NPTS];
__device__ unsigned g_hist_part[BATCH * PARTS * NBINS];
__device__ unsigned g_partoff[BATCH * PARTS * NBINS];
__device__ int g_binstart[BATCH * NBINS];
__device__ float g_cbmin[BATCH * NCHK];
__device__ float g_cbmax[BATCH * NCHK];
__device__ int g_knn_idx[BATCH * NQUERY * NS];

__device__ __forceinline__ int binof(float x) {
    int b = (int)((x + 4.5f) * (NBINS / 9.0f));
    return min(max(b, 0), NBINS - 1);
}

// ---------------------------------------------------------------- prep ----
__global__ void hist_kernel(const float* __restrict__ xyz) {
    __shared__ unsigned h[NBINS];
    const int b = blockIdx.x / PARTS, p = blockIdx.x % PARTS;
    const int tid = threadIdx.x;
    for (int i = tid; i < NBINS; i += 256) h[i] = 0;
    __syncthreads();
    const int base = p * PPTS;
    for (int i = tid; i < PPTS; i += 256) {
        float x = xyz[((size_t)b * NPTS + base + i) * 3];
        atomicAdd(&h[binof(x)], 1u);
    }
    __syncthreads();
    for (int i = tid; i < NBINS; i += 256)
        g_hist_part[((size_t)b * PARTS + p) * NBINS + i] = h[i];
}

__global__ void scan_kernel() {
    __shared__ unsigned wsum[8];
    __shared__ int sstart[NBINS];
    const int b = blockIdx.x;
    const int tid = threadIdx.x;          // == bin, 256 threads
    const int lane = tid & 31, wid = tid >> 5;

    unsigned v = 0;
    #pragma unroll
    for (int p = 0; p < PARTS; p++)
        v += g_hist_part[((size_t)b * PARTS + p) * NBINS + tid];

    unsigned incl = v;                    // block-wide exclusive scan
    #pragma unroll
    for (int off = 1; off < 32; off <<= 1) {
        unsigned t = __shfl_up_sync(FULLMASK, incl, off);
        if (lane >= off) incl += t;
    }
    if (lane == 31) wsum[wid] = incl;
    __syncthreads();
    if (wid == 0) {
        unsigned s = (lane < 8) ? wsum[lane] : 0, o = s;
        #pragma unroll
        for (int off = 1; off < 8; off <<= 1) {
            unsigned t = __shfl_up_sync(FULLMASK, s, off);
            if (lane >= off) s += t;
        }
        if (lane < 8) wsum[lane] = s - o;
    }
    __syncthreads();
    unsigned excl = incl - v + wsum[wid];
    sstart[tid] = (int)excl;
    g_binstart[b * NBINS + tid] = (int)excl;

    unsigned run = excl;                  // per-part cursors
    #pragma unroll
    for (int p = 0; p < PARTS; p++) {
        g_partoff[((size_t)b * PARTS + p) * NBINS + tid] = run;
        run += g_hist_part[((size_t)b * PARTS + p) * NBINS + tid];
    }
    __syncthreads();

    if (tid < NCHK) {                     // conservative chunk x-bounds
        int posL = tid * 128, posR = posL + 127;
        int lo = 0, hi = NBINS - 1;       // last bin with start <= posL
        while (lo < hi) { int m = (lo + hi + 1) >> 1;
                          if (sstart[m] <= posL) lo = m; else hi = m - 1; }
        int binL = lo;
        lo = binL; hi = NBINS - 1;        // last bin with start <= posR
        while (lo < hi) { int m = (lo + hi + 1) >> 1;
                          if (sstart[m] <= posR) lo = m; else hi = m - 1; }
        int binR = lo;
        float eL = (binL == 0) ? -1e30f
                 : binL * (9.0f / NBINS) - 4.5f - 1e-3f;
        float eR = (binR == NBINS - 1) ? 1e30f
                 : (binR + 1) * (9.0f / NBINS) - 4.5f + 1e-3f;
        g_cbmin[b * NCHK + tid] = eL;
        g_cbmax[b * NCHK + tid] = eR;
    }
}

__global__ void scatter_kernel(const float* __restrict__ xyz) {
    __shared__ unsigned cur[NBINS];
    const int b = blockIdx.x / PARTS, p = blockIdx.x % PARTS;
    const int tid = threadIdx.x;
    for (int i = tid; i < NBINS; i += 256)
        cur[i] = g_partoff[((size_t)b * PARTS + p) * NBINS + i];
    __syncthreads();
    const int base = p * PPTS;
    for (int i = tid; i < PPTS; i += 256) {
        const float* pt = xyz + ((size_t)b * NPTS + base + i) * 3;
        float x = pt[0], y = pt[1], z = pt[2];
        int pos = (int)atomicAdd(&cur[binof(x)], 1u);
        size_t o = (size_t)b * NPTS + pos;
        g_bx[o] = x; g_by[o] = y; g_bz[o] = z;
        g_bidx[o] = (unsigned short)(base + i);
    }
}

// ------------------------------------------------------------ knn utils ----
__device__ __forceinline__ float sqdist(float qx, float qy, float qz,
                                        float x, float y, float z) {
    // No FMA contraction: matches reference (diff*diff then sum) bit-exactly.
    float dx = qx - x, dy = qy - y, dz = qz - z;
    return __fadd_rn(__fadd_rn(__fmul_rn(dx, dx), __fmul_rn(dy, dy)),
                     __fmul_rn(dz, dz));
}

__device__ __forceinline__ void warp_sort32(unsigned long long& v, int lane) {
    #pragma unroll
    for (int k = 2; k <= 32; k <<= 1) {
        #pragma unroll
        for (int j = k >> 1; j > 0; j >>= 1) {
            unsigned long long o = __shfl_xor_sync(FULLMASK, v, j);
            bool keepMin = (((lane & k) == 0) == ((lane & j) == 0));
            bool less = v < o;
            v = (less == keepMin) ? v : o;
        }
    }
}

// Merge sorted best (asc) with sorted batch p (asc); keep 32 smallest, asc.
__device__ __forceinline__ void warp_merge(unsigned long long& best,
                                           unsigned long long p, int lane) {
    unsigned long long bo = __shfl_sync(FULLMASK, p, 31 - lane);
    unsigned long long v = (best < bo) ? best : bo;
    #pragma unroll
    for (int j = 16; j > 0; j >>= 1) {
        unsigned long long o = __shfl_xor_sync(FULLMASK, v, j);
        bool lower = (lane & j) == 0;
        bool less = v < o;
        v = (less == lower) ? v : o;
    }
    best = v;
}

__device__ __forceinline__ void warp_insert(unsigned long long& best,
                                            unsigned& thrBits,
                                            unsigned long long e,
                                            int lane) {
    unsigned bal = __ballot_sync(FULLMASK, best > e);
    if (bal) {
        int p = __ffs(bal) - 1;
        unsigned long long up = __shfl_up_sync(FULLMASK, best, 1);
        if (lane >= p) best = (lane == p) ? e : up;
    }
    thrBits = (unsigned)(__shfl_sync(FULLMASK, best, 31) >> 32);
}

__device__ __forceinline__ void process_cand(unsigned u, int pidx,
                                             unsigned long long& best,
                                             unsigned& thrBits,
                                             int lane) {
    unsigned q = __ballot_sync(FULLMASK, u <= thrBits);
    if (!q) return;
    unsigned long long k = ((unsigned long long)u << 32) | (unsigned)pidx;
    do {
        int src = __ffs(q) - 1;
        unsigned long long e = __shfl_sync(FULLMASK, k, src);
        warp_insert(best, thrBits, e, lane);
        q &= q - 1;
        q &= __ballot_sync(FULLMASK, u <= thrBits);
    } while (q);
}

// ----------------------------------------------------------------- knn ----
__global__ __launch_bounds__(KNN_THREADS, 3)
void knn_kernel(const float* __restrict__ new_xyz) {
    __shared__ float scmin[NCHK], scmax[NCHK];

    const int blocks_per_batch = NQUERY / QPB;   // 128
    const int b    = blockIdx.x / blocks_per_batch;
    const int qblk = blockIdx.x % blocks_per_batch;

    if (threadIdx.x < NCHK) {
        scmin[threadIdx.x] = g_cbmin[b * NCHK + threadIdx.x];
        scmax[threadIdx.x] = g_cbmax[b * NCHK + threadIdx.x];
    }
    __syncthreads();

    const int w    = threadIdx.x >> 5;
    const int lane = threadIdx.x & 31;
    const int q    = qblk * QPB + w;

    const float4* px = (const float4*)(g_bx + (size_t)b * NPTS);
    const float4* py = (const float4*)(g_by + (size_t)b * NPTS);
    const float4* pz = (const float4*)(g_bz + (size_t)b * NPTS);
    const uint2*  pi = (const uint2*)(g_bidx + (size_t)b * NPTS);

    const float* nq = new_xyz + ((size_t)b * NQUERY + q) * 3;
    const float qx = __ldg(nq), qy = __ldg(nq + 1), qz = __ldg(nq + 2);

    unsigned long long best = ~0ULL;
    unsigned thrBits;

    const int pos0 = __ldg(&g_binstart[b * NBINS + binof(qx)]);
    const int c0 = min(pos0 >> 7, NCHK - 1);

    {   // bootstrap: full sort+merge of the query's own chunk (128 points)
        const int e0 = c0 * 32 + lane;       // float4/uint2 element index
        float4 X = __ldg(px + e0);
        float4 Y = __ldg(py + e0);
        float4 Z = __ldg(pz + e0);
        uint2 pk = __ldg(pi + e0);

        unsigned long long v;
        v = ((unsigned long long)__float_as_uint(sqdist(qx, qy, qz, X.x, Y.x, Z.x)) << 32)
            | (pk.x & 0xffffu);
        warp_sort32(v, lane); warp_merge(best, v, lane);
        v = ((unsigned long long)__float_as_uint(sqdist(qx, qy, qz, X.y, Y.y, Z.y)) << 32)
            | (pk.x >> 16);
        warp_sort32(v, lane); warp_merge(best, v, lane);
        v = ((unsigned long long)__float_as_uint(sqdist(qx, qy, qz, X.z, Y.z, Z.z)) << 32)
            | (pk.y & 0xffffu);
        warp_sort32(v, lane); warp_merge(best, v, lane);
        v = ((unsigned long long)__float_as_uint(sqdist(qx, qy, qz, X.w, Y.w, Z.w)) << 32)
            | (pk.y >> 16);
        warp_sort32(v, lane); warp_merge(best, v, lane);
        thrBits = (unsigned)(__shfl_sync(FULLMASK, best, 31) >> 32);
    }

    int rc = c0 + 1, lc = c0 - 1;
    bool rdone = (rc >= NCHK), ldone = (lc < 0);

    while (!(rdone && ldone)) {
        float thrF = __uint_as_float(thrBits);
        float rb = 0.0f, lb = 0.0f;
        if (!rdone) {
            rb = fmaxf(__fsub_rn(scmin[rc], qx), 0.0f);
            if (__fmul_rn(__fmul_rn(rb, rb), STOP) > thrF) rdone = true;
        }
        if (!ldone) {
            lb = fmaxf(__fsub_rn(qx, scmax[lc]), 0.0f);
            if (__fmul_rn(__fmul_rn(lb, lb), STOP) > thrF) ldone = true;
        }
        if (rdone && ldone) break;

        bool goRight = !rdone && (ldone || rb <= lb);
        int c;
        if (goRight) { c = rc++; if (rc >= NCHK) rdone = true; }
        else         { c = lc--; if (lc < 0)     ldone = true; }

        const int e0 = c * 32 + lane;
        float4 X = __ldg(px + e0);
        float4 Y = __ldg(py + e0);
        float4 Z = __ldg(pz + e0);

        unsigned u0 = __float_as_uint(sqdist(qx, qy, qz, X.x, Y.x, Z.x));
        unsigned u1 = __float_as_uint(sqdist(qx, qy, qz, X.y, Y.y, Z.y));
        unsigned u2 = __float_as_uint(sqdist(qx, qy, qz, X.z, Y.z, Z.z));
        unsigned u3 = __float_as_uint(sqdist(qx, qy, qz, X.w, Y.w, Z.w));

        bool any = (u0 <= thrBits) | (u1 <= thrBits) |
                   (u2 <= thrBits) | (u3 <= thrBits);
        if (__ballot_sync(FULLMASK, any)) {
            uint2 pk = __ldg(pi + e0);
            process_cand(u0, (int)(pk.x & 0xffffu), best, thrBits, lane);
            process_cand(u1, (int)(pk.x >> 16),     best, thrBits, lane);
            process_cand(u2, (int)(pk.y & 0xffffu), best, thrBits, lane);
            process_cand(u3, (int)(pk.y >> 16),     best, thrBits, lane);
        }
    }

    g_knn_idx[((size_t)b * NQUERY + q) * NS + lane] =
        (int)(unsigned)(best & 0xffffffffu);
}

// -------------------------------------------------------------- gather ----
constexpr int OUT_CH = 3 + NCH;                // 67
constexpr int ELEMS  = NQUERY * NS;            // 65536 per (b, ch)
constexpr int GATHER_THREADS = 1024;
constexpr int GSPLIT = 4;

__global__ __launch_bounds__(GATHER_THREADS)
void gather_kernel(const float* __restrict__ xyz,
                   const float* __restrict__ new_xyz,
                   const float* __restrict__ feats,
                   float* __restrict__ out) {
    __shared__ float row[NPTS];
    __shared__ float qrow[NQUERY];
    const int bc   = blockIdx.x / GSPLIT;
    const int half = blockIdx.x % GSPLIT;
    const int b  = bc / OUT_CH;
    const int ch = bc % OUT_CH;

    if (ch >= 3) {
        const float4* src = reinterpret_cast<const float4*>(
            feats + ((size_t)b * NCH + (ch - 3)) * NPTS);
        float4* dst = reinterpret_cast<float4*>(row);
        for (int i = threadIdx.x; i < NPTS / 4; i += GATHER_THREADS) dst[i] = src[i];
    } else {
        const float* src = xyz + (size_t)b * NPTS * 3;
        for (int i = threadIdx.x; i < NPTS; i += GATHER_THREADS)
            row[i] = src[i * 3 + ch];
        const float* qsrc = new_xyz + (size_t)b * NQUERY * 3;
        for (int i = threadIdx.x; i < NQUERY; i += GATHER_THREADS)
            qrow[i] = qsrc[i * 3 + ch];
    }
    __syncthreads();

    const int4* idx4 = reinterpret_cast<const int4*>(g_knn_idx + (size_t)b * ELEMS);
    float4* ob4 = reinterpret_cast<float4*>(out + ((size_t)b * OUT_CH + ch) * ELEMS);

    constexpr int NV  = ELEMS / 4;             // 16384 float4 per (b, ch)
    constexpr int NVH = NV / GSPLIT;           // 4096 per block
    const int e0 = half * NVH;

    if (ch >= 3) {
        #pragma unroll
        for (int it = 0; it < NVH / GATHER_THREADS; it++) {
            int e = e0 + it * GATHER_THREADS + threadIdx.x;
            int4 n = idx4[e];
            ob4[e] = make_float4(row[n.x], row[n.y], row[n.z], row[n.w]);
        }
    } else {
        #pragma unroll
        for (int it = 0; it < NVH / GATHER_THREADS; it++) {
            int e = e0 + it * GATHER_THREADS + threadIdx.x;
            int4 n = idx4[e];
            float qv = qrow[e >> 3];
            float4 v;
            v.x = __fsub_rn(row[n.x], qv);
            v.y = __fsub_rn(row[n.y], qv);
            v.z = __fsub_rn(row[n.z], qv);
            v.w = __fsub_rn(row[n.w], qv);
            ob4[e] = v;
        }
    }
}

// -------------------------------------------------------------- launch ----
extern "C" void kernel_launch(void* const* d_in, const int* in_sizes, int n_in,
                              void* d_out, int out_size) {
    const float* xyz      = (const float*)d_in[0];   // (4, 8192, 3) f32
    const float* new_xyz  = (const float*)d_in[1];   // (4, 2048, 3) f32
    // d_in[2], d_in[3]: components (int64) -- dead (LAMBDA = 0.5)
    const float* feats    = (const float*)d_in[4];   // (4, 64, 8192) f32
    float* out = (float*)d_out;                      // (4, 67, 2048, 32) f32

    hist_kernel<<<BATCH * PARTS, 256>>>(xyz);
    scan_kernel<<<BATCH, 256>>>();
    scatter_kernel<<<BATCH * PARTS, 256>>>(xyz);
    knn_kernel<<<BATCH * (NQUERY / QPB), KNN_THREADS>>>(new_xyz);
    gather_kernel<<<BATCH * OUT_CH * GSPLIT, GATHER_THREADS>>>(xyz, new_xyz,
                                                               feats, out);
}

// round 8
// speedup vs baseline: 2.4889x; 1.0218x over previous
#include <cuda_runtime.h>
#include <cstdint>

// GAGKNNQueryAndGroup on GB300.
// LAMBDA = 0.5 -> lam == 1-lam: rescale scales every distance by 0.5 uniformly,
// ordering is plain squared-distance KNN; components inputs dead.
//
// R8 = R7 + two measured fixes:
//  - knn: QPB 16 -> 4 (128-thr blocks, 12/SM): same 48 warps/SM but 2048
//    fine-grained blocks, so the HW scheduler load-balances the highly
//    variable per-query work; block-retirement tail ~ one query, not 16.
//  - gather: 4 channels per block with float4-interleaved smem rows: each
//    neighbor gather is ONE LDS.128 (was 4 scattered LDS.32 in 4 different
//    blocks); idx array read once per 4 channels (L2 traffic /4); staging is
//    conflict-free STS.128; GSPLIT=2 -> single 136-block wave.
// Exactness: distances use the reference's op order (no FMA); top-32 = 32
// smallest (dist_bits<<32|orig_idx) keys -> order invariant, ties by index ==
// stable argsort; bin-edge prune bounds conservative (margin 1e-3 >> rounding).

#define FULLMASK 0xffffffffu

constexpr int BATCH  = 4;
constexpr int NPTS   = 8192;
constexpr int NQUERY = 2048;
constexpr int NCH    = 64;
constexpr int NS     = 32;
constexpr int NBINS  = 256;
constexpr int NCHK   = NPTS / 128;        // 64 chunks per batch
constexpr int PARTS  = 8;                 // prep blocks per batch
constexpr int PPTS   = NPTS / PARTS;      // 1024 points per prep block
constexpr int QPB    = 4;                 // queries (warps) per knn block
constexpr int KNN_THREADS = QPB * 32;     // 128
constexpr float STOP = 0.9999f;           // conservative prune margin

__device__ float g_bx[BATCH * NPTS];
__device__ float g_by[BATCH * NPTS];
__device__ float g_bz[BATCH * NPTS];
__device__ __align__(16) unsigned short g_bidx[BATCH * NPTS];
__device__ unsigned g_hist_part[BATCH * PARTS * NBINS];
__device__ unsigned g_partoff[BATCH * PARTS * NBINS];
__device__ int g_binstart[BATCH * NBINS];
__device__ float g_cbmin[BATCH * NCHK];
__device__ float g_cbmax[BATCH * NCHK];
__device__ int g_knn_idx[BATCH * NQUERY * NS];

__device__ __forceinline__ int binof(float x) {
    int b = (int)((x + 4.5f) * (NBINS / 9.0f));
    return min(max(b, 0), NBINS - 1);
}

// ---------------------------------------------------------------- prep ----
__global__ void hist_kernel(const float* __restrict__ xyz) {
    __shared__ unsigned h[NBINS];
    const int b = blockIdx.x / PARTS, p = blockIdx.x % PARTS;
    const int tid = threadIdx.x;
    for (int i = tid; i < NBINS; i += 256) h[i] = 0;
    __syncthreads();
    const int base = p * PPTS;
    for (int i = tid; i < PPTS; i += 256) {
        float x = xyz[((size_t)b * NPTS + base + i) * 3];
        atomicAdd(&h[binof(x)], 1u);
    }
    __syncthreads();
    for (int i = tid; i < NBINS; i += 256)
        g_hist_part[((size_t)b * PARTS + p) * NBINS + i] = h[i];
}

__global__ void scan_kernel() {
    __shared__ unsigned wsum[8];
    __shared__ int sstart[NBINS];
    const int b = blockIdx.x;
    const int tid = threadIdx.x;          // == bin, 256 threads
    const int lane = tid & 31, wid = tid >> 5;

    unsigned v = 0;
    #pragma unroll
    for (int p = 0; p < PARTS; p++)
        v += g_hist_part[((size_t)b * PARTS + p) * NBINS + tid];

    unsigned incl = v;                    // block-wide exclusive scan
    #pragma unroll
    for (int off = 1; off < 32; off <<= 1) {
        unsigned t = __shfl_up_sync(FULLMASK, incl, off);
        if (lane >= off) incl += t;
    }
    if (lane == 31) wsum[wid] = incl;
    __syncthreads();
    if (wid == 0) {
        unsigned s = (lane < 8) ? wsum[lane] : 0, o = s;
        #pragma unroll
        for (int off = 1; off < 8; off <<= 1) {
            unsigned t = __shfl_up_sync(FULLMASK, s, off);
            if (lane >= off) s += t;
        }
        if (lane < 8) wsum[lane] = s - o;
    }
    __syncthreads();
    unsigned excl = incl - v + wsum[wid];
    sstart[tid] = (int)excl;
    g_binstart[b * NBINS + tid] = (int)excl;

    unsigned run = excl;                  // per-part cursors
    #pragma unroll
    for (int p = 0; p < PARTS; p++) {
        g_partoff[((size_t)b * PARTS + p) * NBINS + tid] = run;
        run += g_hist_part[((size_t)b * PARTS + p) * NBINS + tid];
    }
    __syncthreads();

    if (tid < NCHK) {                     // conservative chunk x-bounds
        int posL = tid * 128, posR = posL + 127;
        int lo = 0, hi = NBINS - 1;       // last bin with start <= posL
        while (lo < hi) { int m = (lo + hi + 1) >> 1;
                          if (sstart[m] <= posL) lo = m; else hi = m - 1; }
        int binL = lo;
        lo = binL; hi = NBINS - 1;        // last bin with start <= posR
        while (lo < hi) { int m = (lo + hi + 1) >> 1;
                          if (sstart[m] <= posR) lo = m; else hi = m - 1; }
        int binR = lo;
        float eL = (binL == 0) ? -1e30f
                 : binL * (9.0f / NBINS) - 4.5f - 1e-3f;
        float eR = (binR == NBINS - 1) ? 1e30f
                 : (binR + 1) * (9.0f / NBINS) - 4.5f + 1e-3f;
        g_cbmin[b * NCHK + tid] = eL;
        g_cbmax[b * NCHK + tid] = eR;
    }
}

__global__ void scatter_kernel(const float* __restrict__ xyz) {
    __shared__ unsigned cur[NBINS];
    const int b = blockIdx.x / PARTS, p = blockIdx.x % PARTS;
    const int tid = threadIdx.x;
    for (int i = tid; i < NBINS; i += 256)
        cur[i] = g_partoff[((size_t)b * PARTS + p) * NBINS + i];
    __syncthreads();
    const int base = p * PPTS;
    for (int i = tid; i < PPTS; i += 256) {
        const float* pt = xyz + ((size_t)b * NPTS + base + i) * 3;
        float x = pt[0], y = pt[1], z = pt[2];
        int pos = (int)atomicAdd(&cur[binof(x)], 1u);
        size_t o = (size_t)b * NPTS + pos;
        g_bx[o] = x; g_by[o] = y; g_bz[o] = z;
        g_bidx[o] = (unsigned short)(base + i);
    }
}

// ------------------------------------------------------------ knn utils ----
__device__ __forceinline__ float sqdist(float qx, float qy, float qz,
                                        float x, float y, float z) {
    // No FMA contraction: matches reference (diff*diff then sum) bit-exactly.
    float dx = qx - x, dy = qy - y, dz = qz - z;
    return __fadd_rn(__fadd_rn(__fmul_rn(dx, dx), __fmul_rn(dy, dy)),
                     __fmul_rn(dz, dz));
}

__device__ __forceinline__ void warp_sort32(unsigned long long& v, int lane) {
    #pragma unroll
    for (int k = 2; k <= 32; k <<= 1) {
        #pragma unroll
        for (int j = k >> 1; j > 0; j >>= 1) {
            unsigned long long o = __shfl_xor_sync(FULLMASK, v, j);
            bool keepMin = (((lane & k) == 0) == ((lane & j) == 0));
            bool less = v < o;
            v = (less == keepMin) ? v : o;
        }
    }
}

// Merge sorted best (asc) with sorted batch p (asc); keep 32 smallest, asc.
__device__ __forceinline__ void warp_merge(unsigned long long& best,
                                           unsigned long long p, int lane) {
    unsigned long long bo = __shfl_sync(FULLMASK, p, 31 - lane);
    unsigned long long v = (best < bo) ? best : bo;
    #pragma unroll
    for (int j = 16; j > 0; j >>= 1) {
        unsigned long long o = __shfl_xor_sync(FULLMASK, v, j);
        bool lower = (lane & j) == 0;
        bool less = v < o;
        v = (less == lower) ? v : o;
    }
    best = v;
}

__device__ __forceinline__ void warp_insert(unsigned long long& best,
                                            unsigned& thrBits,
                                            unsigned long long e,
                                            int lane) {
    unsigned bal = __ballot_sync(FULLMASK, best > e);
    if (bal) {
        int p = __ffs(bal) - 1;
        unsigned long long up = __shfl_up_sync(FULLMASK, best, 1);
        if (lane >= p) best = (lane == p) ? e : up;
    }
    thrBits = (unsigned)(__shfl_sync(FULLMASK, best, 31) >> 32);
}

__device__ __forceinline__ void process_cand(unsigned u, int pidx,
                                             unsigned long long& best,
                                             unsigned& thrBits,
                                             int lane) {
    unsigned q = __ballot_sync(FULLMASK, u <= thrBits);
    if (!q) return;
    unsigned long long k = ((unsigned long long)u << 32) | (unsigned)pidx;
    do {
        int src = __ffs(q) - 1;
        unsigned long long e = __shfl_sync(FULLMASK, k, src);
        warp_insert(best, thrBits, e, lane);
        q &= q - 1;
        q &= __ballot_sync(FULLMASK, u <= thrBits);
    } while (q);
}

// ----------------------------------------------------------------- knn ----
__global__ __launch_bounds__(KNN_THREADS, 12)
void knn_kernel(const float* __restrict__ new_xyz) {
    __shared__ float scmin[NCHK], scmax[NCHK];

    const int blocks_per_batch = NQUERY / QPB;   // 512
    const int b    = blockIdx.x / blocks_per_batch;
    const int qblk = blockIdx.x % blocks_per_batch;

    if (threadIdx.x < NCHK) {
        scmin[threadIdx.x] = g_cbmin[b * NCHK + threadIdx.x];
        scmax[threadIdx.x] = g_cbmax[b * NCHK + threadIdx.x];
    }
    __syncthreads();

    const int w    = threadIdx.x >> 5;
    const int lane = threadIdx.x & 31;
    const int q    = qblk * QPB + w;

    const float4* px = (const float4*)(g_bx + (size_t)b * NPTS);
    const float4* py = (const float4*)(g_by + (size_t)b * NPTS);
    const float4* pz = (const float4*)(g_bz + (size_t)b * NPTS);
    const uint2*  pi = (const uint2*)(g_bidx + (size_t)b * NPTS);

    const float* nq = new_xyz + ((size_t)b * NQUERY + q) * 3;
    const float qx = __ldg(nq), qy = __ldg(nq + 1), qz = __ldg(nq + 2);

    unsigned long long best = ~0ULL;
    unsigned thrBits;

    const int pos0 = __ldg(&g_binstart[b * NBINS + binof(qx)]);
    const int c0 = min(pos0 >> 7, NCHK - 1);

    {   // bootstrap: full sort+merge of the query's own chunk (128 points)
        const int e0 = c0 * 32 + lane;       // float4/uint2 element index
        float4 X = __ldg(px + e0);
        float4 Y = __ldg(py + e0);
        float4 Z = __ldg(pz + e0);
        uint2 pk = __ldg(pi + e0);

        unsigned long long v;
        v = ((unsigned long long)__float_as_uint(sqdist(qx, qy, qz, X.x, Y.x, Z.x)) << 32)
            | (pk.x & 0xffffu);
        warp_sort32(v, lane); warp_merge(best, v, lane);
        v = ((unsigned long long)__float_as_uint(sqdist(qx, qy, qz, X.y, Y.y, Z.y)) << 32)
            | (pk.x >> 16);
        warp_sort32(v, lane); warp_merge(best, v, lane);
        v = ((unsigned long long)__float_as_uint(sqdist(qx, qy, qz, X.z, Y.z, Z.z)) << 32)
            | (pk.y & 0xffffu);
        warp_sort32(v, lane); warp_merge(best, v, lane);
        v = ((unsigned long long)__float_as_uint(sqdist(qx, qy, qz, X.w, Y.w, Z.w)) << 32)
            | (pk.y >> 16);
        warp_sort32(v, lane); warp_merge(best, v, lane);
        thrBits = (unsigned)(__shfl_sync(FULLMASK, best, 31) >> 32);
    }

    int rc = c0 + 1, lc = c0 - 1;
    bool rdone = (rc >= NCHK), ldone = (lc < 0);

    while (!(rdone && ldone)) {
        float thrF = __uint_as_float(thrBits);
        float rb = 0.0f, lb = 0.0f;
        if (!rdone) {
            rb = fmaxf(__fsub_rn(scmin[rc], qx), 0.0f);
            if (__fmul_rn(__fmul_rn(rb, rb), STOP) > thrF) rdone = true;
        }
        if (!ldone) {
            lb = fmaxf(__fsub_rn(qx, scmax[lc]), 0.0f);
            if (__fmul_rn(__fmul_rn(lb, lb), STOP) > thrF) ldone = true;
        }
        if (rdone && ldone) break;

        bool goRight = !rdone && (ldone || rb <= lb);
        int c;
        if (goRight) { c = rc++; if (rc >= NCHK) rdone = true; }
        else         { c = lc--; if (lc < 0)     ldone = true; }

        const int e0 = c * 32 + lane;
        float4 X = __ldg(px + e0);
        float4 Y = __ldg(py + e0);
        float4 Z = __ldg(pz + e0);

        unsigned u0 = __float_as_uint(sqdist(qx, qy, qz, X.x, Y.x, Z.x));
        unsigned u1 = __float_as_uint(sqdist(qx, qy, qz, X.y, Y.y, Z.y));
        unsigned u2 = __float_as_uint(sqdist(qx, qy, qz, X.z, Y.z, Z.z));
        unsigned u3 = __float_as_uint(sqdist(qx, qy, qz, X.w, Y.w, Z.w));

        bool any = (u0 <= thrBits) | (u1 <= thrBits) |
                   (u2 <= thrBits) | (u3 <= thrBits);
        if (__ballot_sync(FULLMASK, any)) {
            uint2 pk = __ldg(pi + e0);
            process_cand(u0, (int)(pk.x & 0xffffu), best, thrBits, lane);
            process_cand(u1, (int)(pk.x >> 16),     best, thrBits, lane);
            process_cand(u2, (int)(pk.y & 0xffffu), best, thrBits, lane);
            process_cand(u3, (int)(pk.y >> 16),     best, thrBits, lane);
        }
    }

    g_knn_idx[((size_t)b * NQUERY + q) * NS + lane] =
        (int)(unsigned)(best & 0xffffffffu);
}

// -------------------------------------------------------------- gather ----
// One block handles 4 output channels (group). Group 0 = xyz (3 channels,
// query-subtracted); groups 1..16 = feature channels 4(g-1)..4(g-1)+3.
// smem: srow4[n] = float4{c0[n],c1[n],c2[n],c3[n]}; neighbor gather is one
// LDS.128. Staging: per point one conflict-free STS.128.
constexpr int OUT_CH = 3 + NCH;                // 67
constexpr int ELEMS  = NQUERY * NS;            // 65536 per (b, ch)
constexpr int NV     = ELEMS / 4;              // 16384 float4 per (b, ch)
constexpr int NGRP   = 17;
constexpr int GSPLIT = 2;
constexpr int GATHER_THREADS = 1024;
constexpr int GATHER_SMEM = (NPTS + NQUERY) * 16;   // 160 KB

__global__ __launch_bounds__(GATHER_THREADS, 1)
void gather_kernel(const float* __restrict__ xyz,
                   const float* __restrict__ new_xyz,
                   const float* __restrict__ feats,
                   float* __restrict__ out) {
    extern __shared__ float4 s4[];
    float4* srow = s4;            // [NPTS]
    float4* sq   = s4 + NPTS;     // [NQUERY] (group 0 only)

    const int half = blockIdx.x % GSPLIT;
    const int bg   = blockIdx.x / GSPLIT;
    const int b    = bg / NGRP;
    const int g    = bg % NGRP;
    const int tid  = threadIdx.x;

    if (g > 0) {
        const int f0 = 4 * (g - 1);
        const float* c0 = feats + ((size_t)b * NCH + f0) * NPTS;
        const float* c1 = c0 + NPTS;
        const float* c2 = c1 + NPTS;
        const float* c3 = c2 + NPTS;
        for (int i = tid; i < NPTS; i += GATHER_THREADS)
            srow[i] = make_float4(__ldg(c0 + i), __ldg(c1 + i),
                                  __ldg(c2 + i), __ldg(c3 + i));
    } else {
        const float* src = xyz + (size_t)b * NPTS * 3;
        for (int i = tid; i < NPTS; i += GATHER_THREADS)
            srow[i] = make_float4(src[3 * i], src[3 * i + 1], src[3 * i + 2], 0.0f);
        const float* qs = new_xyz + (size_t)b * NQUERY * 3;
        for (int i = tid; i < NQUERY; i += GATHER_THREADS)
            sq[i] = make_float4(qs[3 * i], qs[3 * i + 1], qs[3 * i + 2], 0.0f);
    }
    __syncthreads();

    const int4* idx4 = reinterpret_cast<const int4*>(g_knn_idx + (size_t)b * ELEMS);
    constexpr int NVH = NV / GSPLIT;            // 8192 per block
    const int e0 = half * NVH;

    if (g > 0) {
        const int ch0 = 3 + 4 * (g - 1);
        float4* o = reinterpret_cast<float4*>(out + ((size_t)b * OUT_CH + ch0) * ELEMS);
        #pragma unroll
        for (int it = 0; it < NVH / GATHER_THREADS; it++) {
            int e = e0 + it * GATHER_THREADS + tid;
            int4 n = idx4[e];
            float4 p0 = srow[n.x], p1 = srow[n.y], p2 = srow[n.z], p3 = srow[n.w];
            o[e]          = make_float4(p0.x, p1.x, p2.x, p3.x);
            o[e + NV]     = make_float4(p0.y, p1.y, p2.y, p3.y);
            o[e + 2 * NV] = make_float4(p0.z, p1.z, p2.z, p3.z);
            o[e + 3 * NV] = make_float4(p0.w, p1.w, p2.w, p3.w);
        }
    } else {
        float4* o = reinterpret_cast<float4*>(out + (size_t)b * OUT_CH * ELEMS);
        #pragma unroll
        for (int it = 0; it < NVH / GATHER_THREADS; it++) {
            int e = e0 + it * GATHER_THREADS + tid;
            int4 n = idx4[e];
            float4 p0 = srow[n.x], p1 = srow[n.y], p2 = srow[n.z], p3 = srow[n.w];
            float4 qv = sq[e >> 3];             // query = (4e)/32
            o[e]          = make_float4(__fsub_rn(p0.x, qv.x), __fsub_rn(p1.x, qv.x),
                                        __fsub_rn(p2.x, qv.x), __fsub_rn(p3.x, qv.x));
            o[e + NV]     = make_float4(__fsub_rn(p0.y, qv.y), __fsub_rn(p1.y, qv.y),
                                        __fsub_rn(p2.y, qv.y), __fsub_rn(p3.y, qv.y));
            o[e + 2 * NV] = make_float4(__fsub_rn(p0.z, qv.z), __fsub_rn(p1.z, qv.z),
                                        __fsub_rn(p2.z, qv.z), __fsub_rn(p3.z, qv.z));
        }
    }
}

// -------------------------------------------------------------- launch ----
extern "C" void kernel_launch(void* const* d_in, const int* in_sizes, int n_in,
                              void* d_out, int out_size) {
    const float* xyz      = (const float*)d_in[0];   // (4, 8192, 3) f32
    const float* new_xyz  = (const float*)d_in[1];   // (4, 2048, 3) f32
    // d_in[2], d_in[3]: components (int64) -- dead (LAMBDA = 0.5)
    const float* feats    = (const float*)d_in[4];   // (4, 64, 8192) f32
    float* out = (float*)d_out;                      // (4, 67, 2048, 32) f32

    cudaFuncSetAttribute(gather_kernel,
                         cudaFuncAttributeMaxDynamicSharedMemorySize, GATHER_SMEM);

    hist_kernel<<<BATCH * PARTS, 256>>>(xyz);
    scan_kernel<<<BATCH, 256>>>();
    scatter_kernel<<<BATCH * PARTS, 256>>>(xyz);
    knn_kernel<<<BATCH * (NQUERY / QPB), KNN_THREADS>>>(new_xyz);
    gather_kernel<<<BATCH * NGRP * GSPLIT, GATHER_THREADS, GATHER_SMEM>>>(
        xyz, new_xyz, feats, out);
}

// round 9
// speedup vs baseline: 2.6302x; 1.0568x over previous
#include <cuda_runtime.h>
#include <cstdint>

// GAGKNNQueryAndGroup on GB300.
// LAMBDA = 0.5 -> lam == 1-lam: rescale scales every distance by 0.5 uniformly,
// ordering is plain squared-distance KNN; components inputs dead.
//
// R9 = R8 with the serialized per-candidate insert chains replaced by a
// per-warp SMEM candidate buffer + batched warp bitonic sort32/merge:
//  - append: ballot -> popc-prefix -> STS.64 (no dependent shuffles),
//  - drain (when >=32 buffered): LDS.64 + sort32 (15 shfl stages) + merge
//    (6 stages) folds 32 candidates in ~550 serialized cycles vs ~2500 for
//    32 single inserts. Threshold updates lazily at merges -- still exact:
//    only candidates with u > thr >= final-thr are ever dropped, and the
//    merge keeps the 32 smallest 64-bit keys (order invariant, ties by index
//    == stable argsort).
// R4's batched attempt lost in the register-slot enqueue; SMEM append is ~6
// instrs and only passing lanes do work.

#define FULLMASK 0xffffffffu

constexpr int BATCH  = 4;
constexpr int NPTS   = 8192;
constexpr int NQUERY = 2048;
constexpr int NCH    = 64;
constexpr int NS     = 32;
constexpr int NBINS  = 256;
constexpr int NCHK   = NPTS / 128;        // 64 chunks per batch
constexpr int PARTS  = 8;                 // prep blocks per batch
constexpr int PPTS   = NPTS / PARTS;      // 1024 points per prep block
constexpr int QPB    = 4;                 // queries (warps) per knn block
constexpr int KNN_THREADS = QPB * 32;     // 128
constexpr int BUFSZ  = 160;               // per-warp candidate buffer entries
constexpr float STOP = 0.9999f;           // conservative prune margin

__device__ float g_bx[BATCH * NPTS];
__device__ float g_by[BATCH * NPTS];
__device__ float g_bz[BATCH * NPTS];
__device__ __align__(16) unsigned short g_bidx[BATCH * NPTS];
__device__ unsigned g_hist_part[BATCH * PARTS * NBINS];
__device__ unsigned g_partoff[BATCH * PARTS * NBINS];
__device__ int g_binstart[BATCH * NBINS];
__device__ float g_cbmin[BATCH * NCHK];
__device__ float g_cbmax[BATCH * NCHK];
__device__ int g_knn_idx[BATCH * NQUERY * NS];

__device__ __forceinline__ int binof(float x) {
    int b = (int)((x + 4.5f) * (NBINS / 9.0f));
    return min(max(b, 0), NBINS - 1);
}

// ---------------------------------------------------------------- prep ----
__global__ void hist_kernel(const float* __restrict__ xyz) {
    __shared__ unsigned h[NBINS];
    const int b = blockIdx.x / PARTS, p = blockIdx.x % PARTS;
    const int tid = threadIdx.x;
    for (int i = tid; i < NBINS; i += 256) h[i] = 0;
    __syncthreads();
    const int base = p * PPTS;
    for (int i = tid; i < PPTS; i += 256) {
        float x = xyz[((size_t)b * NPTS + base + i) * 3];
        atomicAdd(&h[binof(x)], 1u);
    }
    __syncthreads();
    for (int i = tid; i < NBINS; i += 256)
        g_hist_part[((size_t)b * PARTS + p) * NBINS + i] = h[i];
}

__global__ void scan_kernel() {
    __shared__ unsigned wsum[8];
    __shared__ int sstart[NBINS];
    const int b = blockIdx.x;
    const int tid = threadIdx.x;          // == bin, 256 threads
    const int lane = tid & 31, wid = tid >> 5;

    unsigned v = 0;
    #pragma unroll
    for (int p = 0; p < PARTS; p++)
        v += g_hist_part[((size_t)b * PARTS + p) * NBINS + tid];

    unsigned incl = v;                    // block-wide exclusive scan
    #pragma unroll
    for (int off = 1; off < 32; off <<= 1) {
        unsigned t = __shfl_up_sync(FULLMASK, incl, off);
        if (lane >= off) incl += t;
    }
    if (lane == 31) wsum[wid] = incl;
    __syncthreads();
    if (wid == 0) {
        unsigned s = (lane < 8) ? wsum[lane] : 0, o = s;
        #pragma unroll
        for (int off = 1; off < 8; off <<= 1) {
            unsigned t = __shfl_up_sync(FULLMASK, s, off);
            if (lane >= off) s += t;
        }
        if (lane < 8) wsum[lane] = s - o;
    }
    __syncthreads();
    unsigned excl = incl - v + wsum[wid];
    sstart[tid] = (int)excl;
    g_binstart[b * NBINS + tid] = (int)excl;

    unsigned run = excl;                  // per-part cursors
    #pragma unroll
    for (int p = 0; p < PARTS; p++) {
        g_partoff[((size_t)b * PARTS + p) * NBINS + tid] = run;
        run += g_hist_part[((size_t)b * PARTS + p) * NBINS + tid];
    }
    __syncthreads();

    if (tid < NCHK) {                     // conservative chunk x-bounds
        int posL = tid * 128, posR = posL + 127;
        int lo = 0, hi = NBINS - 1;       // last bin with start <= posL
        while (lo < hi) { int m = (lo + hi + 1) >> 1;
                          if (sstart[m] <= posL) lo = m; else hi = m - 1; }
        int binL = lo;
        lo = binL; hi = NBINS - 1;        // last bin with start <= posR
        while (lo < hi) { int m = (lo + hi + 1) >> 1;
                          if (sstart[m] <= posR) lo = m; else hi = m - 1; }
        int binR = lo;
        float eL = (binL == 0) ? -1e30f
                 : binL * (9.0f / NBINS) - 4.5f - 1e-3f;
        float eR = (binR == NBINS - 1) ? 1e30f
                 : (binR + 1) * (9.0f / NBINS) - 4.5f + 1e-3f;
        g_cbmin[b * NCHK + tid] = eL;
        g_cbmax[b * NCHK + tid] = eR;
    }
}

__global__ void scatter_kernel(const float* __restrict__ xyz) {
    __shared__ unsigned cur[NBINS];
    const int b = blockIdx.x / PARTS, p = blockIdx.x % PARTS;
    const int tid = threadIdx.x;
    for (int i = tid; i < NBINS; i += 256)
        cur[i] = g_partoff[((size_t)b * PARTS + p) * NBINS + i];
    __syncthreads();
    const int base = p * PPTS;
    for (int i = tid; i < PPTS; i += 256) {
        const float* pt = xyz + ((size_t)b * NPTS + base + i) * 3;
        float x = pt[0], y = pt[1], z = pt[2];
        int pos = (int)atomicAdd(&cur[binof(x)], 1u);
        size_t o = (size_t)b * NPTS + pos;
        g_bx[o] = x; g_by[o] = y; g_bz[o] = z;
        g_bidx[o] = (unsigned short)(base + i);
    }
}

// ------------------------------------------------------------ knn utils ----
__device__ __forceinline__ float sqdist(float qx, float qy, float qz,
                                        float x, float y, float z) {
    // No FMA contraction: matches reference (diff*diff then sum) bit-exactly.
    float dx = qx - x, dy = qy - y, dz = qz - z;
    return __fadd_rn(__fadd_rn(__fmul_rn(dx, dx), __fmul_rn(dy, dy)),
                     __fmul_rn(dz, dz));
}

__device__ __forceinline__ void warp_sort32(unsigned long long& v, int lane) {
    #pragma unroll
    for (int k = 2; k <= 32; k <<= 1) {
        #pragma unroll
        for (int j = k >> 1; j > 0; j >>= 1) {
            unsigned long long o = __shfl_xor_sync(FULLMASK, v, j);
            bool keepMin = (((lane & k) == 0) == ((lane & j) == 0));
            bool less = v < o;
            v = (less == keepMin) ? v : o;
        }
    }
}

// Merge sorted best (asc) with sorted batch p (asc); keep 32 smallest, asc.
__device__ __forceinline__ void warp_merge(unsigned long long& best,
                                           unsigned long long p, int lane) {
    unsigned long long bo = __shfl_sync(FULLMASK, p, 31 - lane);
    unsigned long long v = (best < bo) ? best : bo;
    #pragma unroll
    for (int j = 16; j > 0; j >>= 1) {
        unsigned long long o = __shfl_xor_sync(FULLMASK, v, j);
        bool lower = (lane & j) == 0;
        bool less = v < o;
        v = (less == lower) ? v : o;
    }
    best = v;
}

// ----------------------------------------------------------------- knn ----
__global__ __launch_bounds__(KNN_THREADS, 12)
void knn_kernel(const float* __restrict__ new_xyz) {
    __shared__ float scmin[NCHK], scmax[NCHK];
    __shared__ unsigned long long sbuf[QPB][BUFSZ];

    const int blocks_per_batch = NQUERY / QPB;   // 512
    const int b    = blockIdx.x / blocks_per_batch;
    const int qblk = blockIdx.x % blocks_per_batch;

    if (threadIdx.x < NCHK) {
        scmin[threadIdx.x] = g_cbmin[b * NCHK + threadIdx.x];
        scmax[threadIdx.x] = g_cbmax[b * NCHK + threadIdx.x];
    }
    __syncthreads();

    const int w    = threadIdx.x >> 5;
    const int lane = threadIdx.x & 31;
    const int q    = qblk * QPB + w;
    unsigned long long* buf = sbuf[w];

    const float4* px = (const float4*)(g_bx + (size_t)b * NPTS);
    const float4* py = (const float4*)(g_by + (size_t)b * NPTS);
    const float4* pz = (const float4*)(g_bz + (size_t)b * NPTS);
    const uint2*  pi = (const uint2*)(g_bidx + (size_t)b * NPTS);

    const float* nq = new_xyz + ((size_t)b * NQUERY + q) * 3;
    const float qx = __ldg(nq), qy = __ldg(nq + 1), qz = __ldg(nq + 2);

    unsigned long long best = ~0ULL;
    unsigned thrBits;
    int cnt = 0;                          // buffered candidates (warp-uniform)
    const unsigned lmask = (1u << lane) - 1u;

    const int pos0 = __ldg(&g_binstart[b * NBINS + binof(qx)]);
    const int c0 = min(pos0 >> 7, NCHK - 1);

    {   // bootstrap: full sort+merge of the query's own chunk (128 points)
        const int e0 = c0 * 32 + lane;
        float4 X = __ldg(px + e0);
        float4 Y = __ldg(py + e0);
        float4 Z = __ldg(pz + e0);
        uint2 pk = __ldg(pi + e0);

        unsigned long long v;
        v = ((unsigned long long)__float_as_uint(sqdist(qx, qy, qz, X.x, Y.x, Z.x)) << 32)
            | (pk.x & 0xffffu);
        warp_sort32(v, lane); warp_merge(best, v, lane);
        v = ((unsigned long long)__float_as_uint(sqdist(qx, qy, qz, X.y, Y.y, Z.y)) << 32)
            | (pk.x >> 16);
        warp_sort32(v, lane); warp_merge(best, v, lane);
        v = ((unsigned long long)__float_as_uint(sqdist(qx, qy, qz, X.z, Y.z, Z.z)) << 32)
            | (pk.y & 0xffffu);
        warp_sort32(v, lane); warp_merge(best, v, lane);
        v = ((unsigned long long)__float_as_uint(sqdist(qx, qy, qz, X.w, Y.w, Z.w)) << 32)
            | (pk.y >> 16);
        warp_sort32(v, lane); warp_merge(best, v, lane);
        thrBits = (unsigned)(__shfl_sync(FULLMASK, best, 31) >> 32);
    }

    int rc = c0 + 1, lc = c0 - 1;
    bool rdone = (rc >= NCHK), ldone = (lc < 0);

    while (!(rdone && ldone)) {
        float thrF = __uint_as_float(thrBits);
        float rb = 0.0f, lb = 0.0f;
        if (!rdone) {
            rb = fmaxf(__fsub_rn(scmin[rc], qx), 0.0f);
            if (__fmul_rn(__fmul_rn(rb, rb), STOP) > thrF) rdone = true;
        }
        if (!ldone) {
            lb = fmaxf(__fsub_rn(qx, scmax[lc]), 0.0f);
            if (__fmul_rn(__fmul_rn(lb, lb), STOP) > thrF) ldone = true;
        }
        if (rdone && ldone) break;

        bool goRight = !rdone && (ldone || rb <= lb);
        int c;
        if (goRight) { c = rc++; if (rc >= NCHK) rdone = true; }
        else         { c = lc--; if (lc < 0)     ldone = true; }

        const int e0 = c * 32 + lane;
        float4 X = __ldg(px + e0);
        float4 Y = __ldg(py + e0);
        float4 Z = __ldg(pz + e0);

        unsigned u0 = __float_as_uint(sqdist(qx, qy, qz, X.x, Y.x, Z.x));
        unsigned u1 = __float_as_uint(sqdist(qx, qy, qz, X.y, Y.y, Z.y));
        unsigned u2 = __float_as_uint(sqdist(qx, qy, qz, X.z, Y.z, Z.z));
        unsigned u3 = __float_as_uint(sqdist(qx, qy, qz, X.w, Y.w, Z.w));

        unsigned mn = min(min(u0, u1), min(u2, u3));
        if (!__ballot_sync(FULLMASK, mn <= thrBits)) continue;

        uint2 pk = __ldg(pi + e0);
        // append passing candidates: ballot -> popc prefix -> STS.64
        unsigned m0 = __ballot_sync(FULLMASK, u0 <= thrBits);
        if (m0) {
            if ((m0 >> lane) & 1u)
                buf[cnt + __popc(m0 & lmask)] =
                    ((unsigned long long)u0 << 32) | (pk.x & 0xffffu);
            cnt += __popc(m0);
        }
        unsigned m1 = __ballot_sync(FULLMASK, u1 <= thrBits);
        if (m1) {
            if ((m1 >> lane) & 1u)
                buf[cnt + __popc(m1 & lmask)] =
                    ((unsigned long long)u1 << 32) | (pk.x >> 16);
            cnt += __popc(m1);
        }
        unsigned m2 = __ballot_sync(FULLMASK, u2 <= thrBits);
        if (m2) {
            if ((m2 >> lane) & 1u)
                buf[cnt + __popc(m2 & lmask)] =
                    ((unsigned long long)u2 << 32) | (pk.y & 0xffffu);
            cnt += __popc(m2);
        }
        unsigned m3 = __ballot_sync(FULLMASK, u3 <= thrBits);
        if (m3) {
            if ((m3 >> lane) & 1u)
                buf[cnt + __popc(m3 & lmask)] =
                    ((unsigned long long)u3 << 32) | (pk.y >> 16);
            cnt += __popc(m3);
        }

        // drain to < 32 (LIFO: newest entries have tightest implicit thr)
        while (cnt >= 32) {
            __syncwarp(FULLMASK);
            unsigned long long v = buf[cnt - 32 + lane];
            cnt -= 32;
            warp_sort32(v, lane);
            warp_merge(best, v, lane);
            thrBits = (unsigned)(__shfl_sync(FULLMASK, best, 31) >> 32);
        }
    }

    if (cnt > 0) {       // final flush
        __syncwarp(FULLMASK);
        unsigned long long v = (lane < cnt) ? buf[lane] : ~0ULL;
        warp_sort32(v, lane);
        warp_merge(best, v, lane);
    }

    g_knn_idx[((size_t)b * NQUERY + q) * NS + lane] =
        (int)(unsigned)(best & 0xffffffffu);
}

// -------------------------------------------------------------- gather ----
constexpr int OUT_CH = 3 + NCH;                // 67
constexpr int ELEMS  = NQUERY * NS;            // 65536 per (b, ch)
constexpr int NV     = ELEMS / 4;              // 16384 float4 per (b, ch)
constexpr int NGRP   = 17;
constexpr int GSPLIT = 2;
constexpr int GATHER_THREADS = 1024;
constexpr int GATHER_SMEM = (NPTS + NQUERY) * 16;   // 160 KB

__global__ __launch_bounds__(GATHER_THREADS, 1)
void gather_kernel(const float* __restrict__ xyz,
                   const float* __restrict__ new_xyz,
                   const float* __restrict__ feats,
                   float* __restrict__ out) {
    extern __shared__ float4 s4[];
    float4* srow = s4;            // [NPTS]
    float4* sq   = s4 + NPTS;     // [NQUERY] (group 0 only)

    const int half = blockIdx.x % GSPLIT;
    const int bg   = blockIdx.x / GSPLIT;
    const int b    = bg / NGRP;
    const int g    = bg % NGRP;
    const int tid  = threadIdx.x;

    if (g > 0) {
        const int f0 = 4 * (g - 1);
        const float* c0 = feats + ((size_t)b * NCH + f0) * NPTS;
        const float* c1 = c0 + NPTS;
        const float* c2 = c1 + NPTS;
        const float* c3 = c2 + NPTS;
        for (int i = tid; i < NPTS; i += GATHER_THREADS)
            srow[i] = make_float4(__ldg(c0 + i), __ldg(c1 + i),
                                  __ldg(c2 + i), __ldg(c3 + i));
    } else {
        const float* src = xyz + (size_t)b * NPTS * 3;
        for (int i = tid; i < NPTS; i += GATHER_THREADS)
            srow[i] = make_float4(src[3 * i], src[3 * i + 1], src[3 * i + 2], 0.0f);
        const float* qs = new_xyz + (size_t)b * NQUERY * 3;
        for (int i = tid; i < NQUERY; i += GATHER_THREADS)
            sq[i] = make_float4(qs[3 * i], qs[3 * i + 1], qs[3 * i + 2], 0.0f);
    }
    __syncthreads();

    const int4* idx4 = reinterpret_cast<const int4*>(g_knn_idx + (size_t)b * ELEMS);
    constexpr int NVH = NV / GSPLIT;            // 8192 per block
    const int e0 = half * NVH;

    if (g > 0) {
        const int ch0 = 3 + 4 * (g - 1);
        float4* o = reinterpret_cast<float4*>(out + ((size_t)b * OUT_CH + ch0) * ELEMS);
        #pragma unroll
        for (int it = 0; it < NVH / GATHER_THREADS; it++) {
            int e = e0 + it * GATHER_THREADS + tid;
            int4 n = idx4[e];
            float4 p0 = srow[n.x], p1 = srow[n.y], p2 = srow[n.z], p3 = srow[n.w];
            o[e]          = make_float4(p0.x, p1.x, p2.x, p3.x);
            o[e + NV]     = make_float4(p0.y, p1.y, p2.y, p3.y);
            o[e + 2 * NV] = make_float4(p0.z, p1.z, p2.z, p3.z);
            o[e + 3 * NV] = make_float4(p0.w, p1.w, p2.w, p3.w);
        }
    } else {
        float4* o = reinterpret_cast<float4*>(out + (size_t)b * OUT_CH * ELEMS);
        #pragma unroll
        for (int it = 0; it < NVH / GATHER_THREADS; it++) {
            int e = e0 + it * GATHER_THREADS + tid;
            int4 n = idx4[e];
            float4 p0 = srow[n.x], p1 = srow[n.y], p2 = srow[n.z], p3 = srow[n.w];
            float4 qv = sq[e >> 3];             // query = (4e)/32
            o[e]          = make_float4(__fsub_rn(p0.x, qv.x), __fsub_rn(p1.x, qv.x),
                                        __fsub_rn(p2.x, qv.x), __fsub_rn(p3.x, qv.x));
            o[e + NV]     = make_float4(__fsub_rn(p0.y, qv.y), __fsub_rn(p1.y, qv.y),
                                        __fsub_rn(p2.y, qv.y), __fsub_rn(p3.y, qv.y));
            o[e + 2 * NV] = make_float4(__fsub_rn(p0.z, qv.z), __fsub_rn(p1.z, qv.z),
                                        __fsub_rn(p2.z, qv.z), __fsub_rn(p3.z, qv.z));
        }
    }
}

// -------------------------------------------------------------- launch ----
extern "C" void kernel_launch(void* const* d_in, const int* in_sizes, int n_in,
                              void* d_out, int out_size) {
    const float* xyz      = (const float*)d_in[0];   // (4, 8192, 3) f32
    const float* new_xyz  = (const float*)d_in[1];   // (4, 2048, 3) f32
    // d_in[2], d_in[3]: components (int64) -- dead (LAMBDA = 0.5)
    const float* feats    = (const float*)d_in[4];   // (4, 64, 8192) f32
    float* out = (float*)d_out;                      // (4, 67, 2048, 32) f32

    cudaFuncSetAttribute(gather_kernel,
                         cudaFuncAttributeMaxDynamicSharedMemorySize, GATHER_SMEM);

    hist_kernel<<<BATCH * PARTS, 256>>>(xyz);
    scan_kernel<<<BATCH, 256>>>();
    scatter_kernel<<<BATCH * PARTS, 256>>>(xyz);
    knn_kernel<<<BATCH * (NQUERY / QPB), KNN_THREADS>>>(new_xyz);
    gather_kernel<<<BATCH * NGRP * GSPLIT, GATHER_THREADS, GATHER_SMEM>>>(
        xyz, new_xyz, feats, out);
}

// round 10
// speedup vs baseline: 2.8886x; 1.0982x over previous
#include <cuda_runtime.h>
#include <cstdint>

// GAGKNNQueryAndGroup on GB300.
// LAMBDA = 0.5 -> lam == 1-lam: rescale scales every distance by 0.5 uniformly,
// ordering is plain squared-distance KNN; components inputs dead.
//
// R10 = R9 with the two-pointer chunk traversal split into two TIGHT phase
// loops (right side fully, then left side). Chunk bin-edge bounds are monotone
// in chunk index, so a one-sided bound test + break is provably safe, deleting
// the dual-side check / direction-select / done-flag scaffolding (~20 instrs
// per chunk -> ~0 beyond one test). Phase order changes candidate processing
// order only -- the kept top-32 (64-bit dist|idx keys) is order invariant, so
// the result is unchanged; thr is near-final after the bootstrap chunk anyway.
// Everything else (prep pipeline, smem-buffered batched sort/merge inserts,
// 4-channel gather) is R9 unchanged.

#define FULLMASK 0xffffffffu

constexpr int BATCH  = 4;
constexpr int NPTS   = 8192;
constexpr int NQUERY = 2048;
constexpr int NCH    = 64;
constexpr int NS     = 32;
constexpr int NBINS  = 256;
constexpr int NCHK   = NPTS / 128;        // 64 chunks per batch
constexpr int PARTS  = 8;                 // prep blocks per batch
constexpr int PPTS   = NPTS / PARTS;      // 1024 points per prep block
constexpr int QPB    = 4;                 // queries (warps) per knn block
constexpr int KNN_THREADS = QPB * 32;     // 128
constexpr int BUFSZ  = 160;               // per-warp candidate buffer entries
constexpr float STOP = 0.9999f;           // conservative prune margin

__device__ float g_bx[BATCH * NPTS];
__device__ float g_by[BATCH * NPTS];
__device__ float g_bz[BATCH * NPTS];
__device__ __align__(16) unsigned short g_bidx[BATCH * NPTS];
__device__ unsigned g_hist_part[BATCH * PARTS * NBINS];
__device__ unsigned g_partoff[BATCH * PARTS * NBINS];
__device__ int g_binstart[BATCH * NBINS];
__device__ float g_cbmin[BATCH * NCHK];
__device__ float g_cbmax[BATCH * NCHK];
__device__ int g_knn_idx[BATCH * NQUERY * NS];

__device__ __forceinline__ int binof(float x) {
    int b = (int)((x + 4.5f) * (NBINS / 9.0f));
    return min(max(b, 0), NBINS - 1);
}

// ---------------------------------------------------------------- prep ----
__global__ void hist_kernel(const float* __restrict__ xyz) {
    __shared__ unsigned h[NBINS];
    const int b = blockIdx.x / PARTS, p = blockIdx.x % PARTS;
    const int tid = threadIdx.x;
    for (int i = tid; i < NBINS; i += 256) h[i] = 0;
    __syncthreads();
    const int base = p * PPTS;
    for (int i = tid; i < PPTS; i += 256) {
        float x = xyz[((size_t)b * NPTS + base + i) * 3];
        atomicAdd(&h[binof(x)], 1u);
    }
    __syncthreads();
    for (int i = tid; i < NBINS; i += 256)
        g_hist_part[((size_t)b * PARTS + p) * NBINS + i] = h[i];
}

__global__ void scan_kernel() {
    __shared__ unsigned wsum[8];
    __shared__ int sstart[NBINS];
    const int b = blockIdx.x;
    const int tid = threadIdx.x;          // == bin, 256 threads
    const int lane = tid & 31, wid = tid >> 5;

    unsigned v = 0;
    #pragma unroll
    for (int p = 0; p < PARTS; p++)
        v += g_hist_part[((size_t)b * PARTS + p) * NBINS + tid];

    unsigned incl = v;                    // block-wide exclusive scan
    #pragma unroll
    for (int off = 1; off < 32; off <<= 1) {
        unsigned t = __shfl_up_sync(FULLMASK, incl, off);
        if (lane >= off) incl += t;
    }
    if (lane == 31) wsum[wid] = incl;
    __syncthreads();
    if (wid == 0) {
        unsigned s = (lane < 8) ? wsum[lane] : 0, o = s;
        #pragma unroll
        for (int off = 1; off < 8; off <<= 1) {
            unsigned t = __shfl_up_sync(FULLMASK, s, off);
            if (lane >= off) s += t;
        }
        if (lane < 8) wsum[lane] = s - o;
    }
    __syncthreads();
    unsigned excl = incl - v + wsum[wid];
    sstart[tid] = (int)excl;
    g_binstart[b * NBINS + tid] = (int)excl;

    unsigned run = excl;                  // per-part cursors
    #pragma unroll
    for (int p = 0; p < PARTS; p++) {
        g_partoff[((size_t)b * PARTS + p) * NBINS + tid] = run;
        run += g_hist_part[((size_t)b * PARTS + p) * NBINS + tid];
    }
    __syncthreads();

    if (tid < NCHK) {                     // conservative, MONOTONE chunk bounds
        int posL = tid * 128, posR = posL + 127;
        int lo = 0, hi = NBINS - 1;       // last bin with start <= posL
        while (lo < hi) { int m = (lo + hi + 1) >> 1;
                          if (sstart[m] <= posL) lo = m; else hi = m - 1; }
        int binL = lo;
        lo = binL; hi = NBINS - 1;        // last bin with start <= posR
        while (lo < hi) { int m = (lo + hi + 1) >> 1;
                          if (sstart[m] <= posR) lo = m; else hi = m - 1; }
        int binR = lo;
        float eL = (binL == 0) ? -1e30f
                 : binL * (9.0f / NBINS) - 4.5f - 1e-3f;
        float eR = (binR == NBINS - 1) ? 1e30f
                 : (binR + 1) * (9.0f / NBINS) - 4.5f + 1e-3f;
        g_cbmin[b * NCHK + tid] = eL;
        g_cbmax[b * NCHK + tid] = eR;
    }
}

__global__ void scatter_kernel(const float* __restrict__ xyz) {
    __shared__ unsigned cur[NBINS];
    const int b = blockIdx.x / PARTS, p = blockIdx.x % PARTS;
    const int tid = threadIdx.x;
    for (int i = tid; i < NBINS; i += 256)
        cur[i] = g_partoff[((size_t)b * PARTS + p) * NBINS + i];
    __syncthreads();
    const int base = p * PPTS;
    for (int i = tid; i < PPTS; i += 256) {
        const float* pt = xyz + ((size_t)b * NPTS + base + i) * 3;
        float x = pt[0], y = pt[1], z = pt[2];
        int pos = (int)atomicAdd(&cur[binof(x)], 1u);
        size_t o = (size_t)b * NPTS + pos;
        g_bx[o] = x; g_by[o] = y; g_bz[o] = z;
        g_bidx[o] = (unsigned short)(base + i);
    }
}

// ------------------------------------------------------------ knn utils ----
__device__ __forceinline__ float sqdist(float qx, float qy, float qz,
                                        float x, float y, float z) {
    // No FMA contraction: matches reference (diff*diff then sum) bit-exactly.
    float dx = qx - x, dy = qy - y, dz = qz - z;
    return __fadd_rn(__fadd_rn(__fmul_rn(dx, dx), __fmul_rn(dy, dy)),
                     __fmul_rn(dz, dz));
}

__device__ __forceinline__ void warp_sort32(unsigned long long& v, int lane) {
    #pragma unroll
    for (int k = 2; k <= 32; k <<= 1) {
        #pragma unroll
        for (int j = k >> 1; j > 0; j >>= 1) {
            unsigned long long o = __shfl_xor_sync(FULLMASK, v, j);
            bool keepMin = (((lane & k) == 0) == ((lane & j) == 0));
            bool less = v < o;
            v = (less == keepMin) ? v : o;
        }
    }
}

// Merge sorted best (asc) with sorted batch p (asc); keep 32 smallest, asc.
__device__ __forceinline__ void warp_merge(unsigned long long& best,
                                           unsigned long long p, int lane) {
    unsigned long long bo = __shfl_sync(FULLMASK, p, 31 - lane);
    unsigned long long v = (best < bo) ? best : bo;
    #pragma unroll
    for (int j = 16; j > 0; j >>= 1) {
        unsigned long long o = __shfl_xor_sync(FULLMASK, v, j);
        bool lower = (lane & j) == 0;
        bool less = v < o;
        v = (less == lower) ? v : o;
    }
    best = v;
}

// ----------------------------------------------------------------- knn ----
__global__ __launch_bounds__(KNN_THREADS, 12)
void knn_kernel(const float* __restrict__ new_xyz) {
    __shared__ float scmin[NCHK], scmax[NCHK];
    __shared__ unsigned long long sbuf[QPB][BUFSZ];

    const int blocks_per_batch = NQUERY / QPB;   // 512
    const int b    = blockIdx.x / blocks_per_batch;
    const int qblk = blockIdx.x % blocks_per_batch;

    if (threadIdx.x < NCHK) {
        scmin[threadIdx.x] = g_cbmin[b * NCHK + threadIdx.x];
        scmax[threadIdx.x] = g_cbmax[b * NCHK + threadIdx.x];
    }
    __syncthreads();

    const int w    = threadIdx.x >> 5;
    const int lane = threadIdx.x & 31;
    const int q    = qblk * QPB + w;
    unsigned long long* buf = sbuf[w];

    const float4* px = (const float4*)(g_bx + (size_t)b * NPTS);
    const float4* py = (const float4*)(g_by + (size_t)b * NPTS);
    const float4* pz = (const float4*)(g_bz + (size_t)b * NPTS);
    const uint2*  pi = (const uint2*)(g_bidx + (size_t)b * NPTS);

    const float* nq = new_xyz + ((size_t)b * NQUERY + q) * 3;
    const float qx = __ldg(nq), qy = __ldg(nq + 1), qz = __ldg(nq + 2);

    unsigned long long best = ~0ULL;
    unsigned thrBits;
    int cnt = 0;                          // buffered candidates (warp-uniform)
    const unsigned lmask = (1u << lane) - 1u;

    const int pos0 = __ldg(&g_binstart[b * NBINS + binof(qx)]);
    const int c0 = min(pos0 >> 7, NCHK - 1);

    {   // bootstrap: full sort+merge of the query's own chunk (128 points)
        const int e0 = c0 * 32 + lane;
        float4 X = __ldg(px + e0);
        float4 Y = __ldg(py + e0);
        float4 Z = __ldg(pz + e0);
        uint2 pk = __ldg(pi + e0);

        unsigned long long v;
        v = ((unsigned long long)__float_as_uint(sqdist(qx, qy, qz, X.x, Y.x, Z.x)) << 32)
            | (pk.x & 0xffffu);
        warp_sort32(v, lane); warp_merge(best, v, lane);
        v = ((unsigned long long)__float_as_uint(sqdist(qx, qy, qz, X.y, Y.y, Z.y)) << 32)
            | (pk.x >> 16);
        warp_sort32(v, lane); warp_merge(best, v, lane);
        v = ((unsigned long long)__float_as_uint(sqdist(qx, qy, qz, X.z, Y.z, Z.z)) << 32)
            | (pk.y & 0xffffu);
        warp_sort32(v, lane); warp_merge(best, v, lane);
        v = ((unsigned long long)__float_as_uint(sqdist(qx, qy, qz, X.w, Y.w, Z.w)) << 32)
            | (pk.y >> 16);
        warp_sort32(v, lane); warp_merge(best, v, lane);
        thrBits = (unsigned)(__shfl_sync(FULLMASK, best, 31) >> 32);
    }

    // scan one 128-point chunk: distances, filtered append, drains
    auto scan_chunk = [&](int c) {
        const int e0 = c * 32 + lane;
        float4 X = __ldg(px + e0);
        float4 Y = __ldg(py + e0);
        float4 Z = __ldg(pz + e0);

        unsigned u0 = __float_as_uint(sqdist(qx, qy, qz, X.x, Y.x, Z.x));
        unsigned u1 = __float_as_uint(sqdist(qx, qy, qz, X.y, Y.y, Z.y));
        unsigned u2 = __float_as_uint(sqdist(qx, qy, qz, X.z, Y.z, Z.z));
        unsigned u3 = __float_as_uint(sqdist(qx, qy, qz, X.w, Y.w, Z.w));

        unsigned mn = min(min(u0, u1), min(u2, u3));
        if (!__ballot_sync(FULLMASK, mn <= thrBits)) return;

        uint2 pk = __ldg(pi + e0);
        unsigned m0 = __ballot_sync(FULLMASK, u0 <= thrBits);
        if (m0) {
            if ((m0 >> lane) & 1u)
                buf[cnt + __popc(m0 & lmask)] =
                    ((unsigned long long)u0 << 32) | (pk.x & 0xffffu);
            cnt += __popc(m0);
        }
        unsigned m1 = __ballot_sync(FULLMASK, u1 <= thrBits);
        if (m1) {
            if ((m1 >> lane) & 1u)
                buf[cnt + __popc(m1 & lmask)] =
                    ((unsigned long long)u1 << 32) | (pk.x >> 16);
            cnt += __popc(m1);
        }
        unsigned m2 = __ballot_sync(FULLMASK, u2 <= thrBits);
        if (m2) {
            if ((m2 >> lane) & 1u)
                buf[cnt + __popc(m2 & lmask)] =
                    ((unsigned long long)u2 << 32) | (pk.y & 0xffffu);
            cnt += __popc(m2);
        }
        unsigned m3 = __ballot_sync(FULLMASK, u3 <= thrBits);
        if (m3) {
            if ((m3 >> lane) & 1u)
                buf[cnt + __popc(m3 & 0xffffffffu & lmask)] =
                    ((unsigned long long)u3 << 32) | (pk.y >> 16);
            cnt += __popc(m3);
        }

        while (cnt >= 32) {               // drain (LIFO)
            __syncwarp(FULLMASK);
            unsigned long long v = buf[cnt - 32 + lane];
            cnt -= 32;
            warp_sort32(v, lane);
            warp_merge(best, v, lane);
            thrBits = (unsigned)(__shfl_sync(FULLMASK, best, 31) >> 32);
        }
    };

    // right phase: scmin monotone non-decreasing -> one-sided test + break safe
    for (int c = c0 + 1; c < NCHK; c++) {
        float rb = fmaxf(__fsub_rn(scmin[c], qx), 0.0f);
        if (__fmul_rn(__fmul_rn(rb, rb), STOP) > __uint_as_float(thrBits)) break;
        scan_chunk(c);
    }
    // left phase: scmax monotone non-increasing going left -> break safe
    for (int c = c0 - 1; c >= 0; c--) {
        float lb = fmaxf(__fsub_rn(qx, scmax[c]), 0.0f);
        if (__fmul_rn(__fmul_rn(lb, lb), STOP) > __uint_as_float(thrBits)) break;
        scan_chunk(c);
    }

    if (cnt > 0) {       // final flush
        __syncwarp(FULLMASK);
        unsigned long long v = (lane < cnt) ? buf[lane] : ~0ULL;
        warp_sort32(v, lane);
        warp_merge(best, v, lane);
    }

    g_knn_idx[((size_t)b * NQUERY + q) * NS + lane] =
        (int)(unsigned)(best & 0xffffffffu);
}

// -------------------------------------------------------------- gather ----
constexpr int OUT_CH = 3 + NCH;                // 67
constexpr int ELEMS  = NQUERY * NS;            // 65536 per (b, ch)
constexpr int NV     = ELEMS / 4;              // 16384 float4 per (b, ch)
constexpr int NGRP   = 17;
constexpr int GSPLIT = 2;
constexpr int GATHER_THREADS = 1024;
constexpr int GATHER_SMEM = (NPTS + NQUERY) * 16;   // 160 KB

__global__ __launch_bounds__(GATHER_THREADS, 1)
void gather_kernel(const float* __restrict__ xyz,
                   const float* __restrict__ new_xyz,
                   const float* __restrict__ feats,
                   float* __restrict__ out) {
    extern __shared__ float4 s4[];
    float4* srow = s4;            // [NPTS]
    float4* sq   = s4 + NPTS;     // [NQUERY] (group 0 only)

    const int half = blockIdx.x % GSPLIT;
    const int bg   = blockIdx.x / GSPLIT;
    const int b    = bg / NGRP;
    const int g    = bg % NGRP;
    const int tid  = threadIdx.x;

    if (g > 0) {
        const int f0 = 4 * (g - 1);
        const float* c0 = feats + ((size_t)b * NCH + f0) * NPTS;
        const float* c1 = c0 + NPTS;
        const float* c2 = c1 + NPTS;
        const float* c3 = c2 + NPTS;
        for (int i = tid; i < NPTS; i += GATHER_THREADS)
            srow[i] = make_float4(__ldg(c0 + i), __ldg(c1 + i),
                                  __ldg(c2 + i), __ldg(c3 + i));
    } else {
        const float* src = xyz + (size_t)b * NPTS * 3;
        for (int i = tid; i < NPTS; i += GATHER_THREADS)
            srow[i] = make_float4(src[3 * i], src[3 * i + 1], src[3 * i + 2], 0.0f);
        const float* qs = new_xyz + (size_t)b * NQUERY * 3;
        for (int i = tid; i < NQUERY; i += GATHER_THREADS)
            sq[i] = make_float4(qs[3 * i], qs[3 * i + 1], qs[3 * i + 2], 0.0f);
    }
    __syncthreads();

    const int4* idx4 = reinterpret_cast<const int4*>(g_knn_idx + (size_t)b * ELEMS);
    constexpr int NVH = NV / GSPLIT;            // 8192 per block
    const int e0 = half * NVH;

    if (g > 0) {
        const int ch0 = 3 + 4 * (g - 1);
        float4* o = reinterpret_cast<float4*>(out + ((size_t)b * OUT_CH + ch0) * ELEMS);
        #pragma unroll
        for (int it = 0; it < NVH / GATHER_THREADS; it++) {
            int e = e0 + it * GATHER_THREADS + tid;
            int4 n = idx4[e];
            float4 p0 = srow[n.x], p1 = srow[n.y], p2 = srow[n.z], p3 = srow[n.w];
            o[e]          = make_float4(p0.x, p1.x, p2.x, p3.x);
            o[e + NV]     = make_float4(p0.y, p1.y, p2.y, p3.y);
            o[e + 2 * NV] = make_float4(p0.z, p1.z, p2.z, p3.z);
            o[e + 3 * NV] = make_float4(p0.w, p1.w, p2.w, p3.w);
        }
    } else {
        float4* o = reinterpret_cast<float4*>(out + (size_t)b * OUT_CH * ELEMS);
        #pragma unroll
        for (int it = 0; it < NVH / GATHER_THREADS; it++) {
            int e = e0 + it * GATHER_THREADS + tid;
            int4 n = idx4[e];
            float4 p0 = srow[n.x], p1 = srow[n.y], p2 = srow[n.z], p3 = srow[n.w];
            float4 qv = sq[e >> 3];             // query = (4e)/32
            o[e]          = make_float4(__fsub_rn(p0.x, qv.x), __fsub_rn(p1.x, qv.x),
                                        __fsub_rn(p2.x, qv.x), __fsub_rn(p3.x, qv.x));
            o[e + NV]     = make_float4(__fsub_rn(p0.y, qv.y), __fsub_rn(p1.y, qv.y),
                                        __fsub_rn(p2.y, qv.y), __fsub_rn(p3.y, qv.y));
            o[e + 2 * NV] = make_float4(__fsub_rn(p0.z, qv.z), __fsub_rn(p1.z, qv.z),
                                        __fsub_rn(p2.z, qv.z), __fsub_rn(p3.z, qv.z));
        }
    }
}

// -------------------------------------------------------------- launch ----
extern "C" void kernel_launch(void* const* d_in, const int* in_sizes, int n_in,
                              void* d_out, int out_size) {
    const float* xyz      = (const float*)d_in[0];   // (4, 8192, 3) f32
    const float* new_xyz  = (const float*)d_in[1];   // (4, 2048, 3) f32
    // d_in[2], d_in[3]: components (int64) -- dead (LAMBDA = 0.5)
    const float* feats    = (const float*)d_in[4];   // (4, 64, 8192) f32
    float* out = (float*)d_out;                      // (4, 67, 2048, 32) f32

    cudaFuncSetAttribute(gather_kernel,
                         cudaFuncAttributeMaxDynamicSharedMemorySize, GATHER_SMEM);

    hist_kernel<<<BATCH * PARTS, 256>>>(xyz);
    scan_kernel<<<BATCH, 256>>>();
    scatter_kernel<<<BATCH * PARTS, 256>>>(xyz);
    knn_kernel<<<BATCH * (NQUERY / QPB), KNN_THREADS>>>(new_xyz);
    gather_kernel<<<BATCH * NGRP * GSPLIT, GATHER_THREADS, GATHER_SMEM>>>(
        xyz, new_xyz, feats, out);
}

// round 11
// speedup vs baseline: 2.9533x; 1.0224x over previous
#include <cuda_runtime.h>
#include <cstdint>

// GAGKNNQueryAndGroup on GB300.
// LAMBDA = 0.5 -> lam == 1-lam: rescale scales every distance by 0.5 uniformly,
// ordering is plain squared-distance KNN; components inputs dead.
//
// R11 = R10 + 2D pruning and a y-local bootstrap:
//  - prep ysort kernel: each 256-pt x-group is sorted by y and split into two
//    128-pt half-chunks with EXACT y bounds (skip tests are continue-only, so
//    non-monotone exact bounds are safe); group x bounds stay bin-edge ->
//    monotone -> break-safe.
//  - knn scans groups (x break) then halves (x+y skip); each evaluated chunk
//    keeps the cheap 4-pt/lane vectorized body.
//  - bootstrap: binary-search qy in the query's (y-sorted) half, sort+merge
//    the 32 contiguous y-nearest points -> near-final thr immediately; rest of
//    the half scanned with those 32 masked out (no duplicate keys).
// Exactness: reference op order for distances (no FMA); top-32 of unique
// 64-bit (dist_bits<<32|idx) keys is processing-order invariant; ties by
// index == stable argsort; prune margin 0.9999 >> fp rounding.

#define FULLMASK 0xffffffffu

constexpr int BATCH  = 4;
constexpr int NPTS   = 8192;
constexpr int NQUERY = 2048;
constexpr int NCH    = 64;
constexpr int NS     = 32;
constexpr int NBINS  = 256;
constexpr int NGR    = 32;                // 256-pt x-groups per batch
constexpr int NCHK   = 64;                // 128-pt y-half chunks per batch
constexpr int PARTS  = 8;
constexpr int PPTS   = NPTS / PARTS;      // 1024
constexpr int QPB    = 4;                 // queries (warps) per knn block
constexpr int KNN_THREADS = QPB * 32;     // 128
constexpr int BUFSZ  = 176;               // per-warp candidate buffer entries
constexpr float STOP = 0.9999f;

__device__ float g_bx[BATCH * NPTS];
__device__ float g_by[BATCH * NPTS];
__device__ float g_bz[BATCH * NPTS];
__device__ __align__(16) unsigned short g_bidx[BATCH * NPTS];
__device__ unsigned g_hist_part[BATCH * PARTS * NBINS];
__device__ unsigned g_partoff[BATCH * PARTS * NBINS];
__device__ int g_binstart[BATCH * NBINS];
__device__ float g_gxmin[BATCH * NGR];
__device__ float g_gxmax[BATCH * NGR];
__device__ float g_cymin[BATCH * NCHK];
__device__ float g_cymax[BATCH * NCHK];
__device__ int g_knn_idx[BATCH * NQUERY * NS];

__device__ __forceinline__ int binof(float x) {
    int b = (int)((x + 4.5f) * (NBINS / 9.0f));
    return min(max(b, 0), NBINS - 1);
}

// ---------------------------------------------------------------- prep ----
__global__ void hist_kernel(const float* __restrict__ xyz) {
    __shared__ unsigned h[NBINS];
    const int b = blockIdx.x / PARTS, p = blockIdx.x % PARTS;
    const int tid = threadIdx.x;
    for (int i = tid; i < NBINS; i += 256) h[i] = 0;
    __syncthreads();
    const int base = p * PPTS;
    for (int i = tid; i < PPTS; i += 256) {
        float x = xyz[((size_t)b * NPTS + base + i) * 3];
        atomicAdd(&h[binof(x)], 1u);
    }
    __syncthreads();
    for (int i = tid; i < NBINS; i += 256)
        g_hist_part[((size_t)b * PARTS + p) * NBINS + i] = h[i];
}

__global__ void scan_kernel() {
    __shared__ unsigned wsum[8];
    __shared__ int sstart[NBINS];
    const int b = blockIdx.x;
    const int tid = threadIdx.x;          // == bin, 256 threads
    const int lane = tid & 31, wid = tid >> 5;

    unsigned v = 0;
    #pragma unroll
    for (int p = 0; p < PARTS; p++)
        v += g_hist_part[((size_t)b * PARTS + p) * NBINS + tid];

    unsigned incl = v;
    #pragma unroll
    for (int off = 1; off < 32; off <<= 1) {
        unsigned t = __shfl_up_sync(FULLMASK, incl, off);
        if (lane >= off) incl += t;
    }
    if (lane == 31) wsum[wid] = incl;
    __syncthreads();
    if (wid == 0) {
        unsigned s = (lane < 8) ? wsum[lane] : 0, o = s;
        #pragma unroll
        for (int off = 1; off < 8; off <<= 1) {
            unsigned t = __shfl_up_sync(FULLMASK, s, off);
            if (lane >= off) s += t;
        }
        if (lane < 8) wsum[lane] = s - o;
    }
    __syncthreads();
    unsigned excl = incl - v + wsum[wid];
    sstart[tid] = (int)excl;
    g_binstart[b * NBINS + tid] = (int)excl;

    unsigned run = excl;
    #pragma unroll
    for (int p = 0; p < PARTS; p++) {
        g_partoff[((size_t)b * PARTS + p) * NBINS + tid] = run;
        run += g_hist_part[((size_t)b * PARTS + p) * NBINS + tid];
    }
    __syncthreads();

    if (tid < NGR) {                      // conservative, MONOTONE group x-bounds
        int posL = tid * 256, posR = posL + 255;
        int lo = 0, hi = NBINS - 1;
        while (lo < hi) { int m = (lo + hi + 1) >> 1;
                          if (sstart[m] <= posL) lo = m; else hi = m - 1; }
        int binL = lo;
        lo = binL; hi = NBINS - 1;
        while (lo < hi) { int m = (lo + hi + 1) >> 1;
                          if (sstart[m] <= posR) lo = m; else hi = m - 1; }
        int binR = lo;
        float eL = (binL == 0) ? -1e30f
                 : binL * (9.0f / NBINS) - 4.5f - 1e-3f;
        float eR = (binR == NBINS - 1) ? 1e30f
                 : (binR + 1) * (9.0f / NBINS) - 4.5f + 1e-3f;
        g_gxmin[b * NGR + tid] = eL;
        g_gxmax[b * NGR + tid] = eR;
    }
}

__global__ void scatter_kernel(const float* __restrict__ xyz) {
    __shared__ unsigned cur[NBINS];
    const int b = blockIdx.x / PARTS, p = blockIdx.x % PARTS;
    const int tid = threadIdx.x;
    for (int i = tid; i < NBINS; i += 256)
        cur[i] = g_partoff[((size_t)b * PARTS + p) * NBINS + i];
    __syncthreads();
    const int base = p * PPTS;
    for (int i = tid; i < PPTS; i += 256) {
        const float* pt = xyz + ((size_t)b * NPTS + base + i) * 3;
        float x = pt[0], y = pt[1], z = pt[2];
        int pos = (int)atomicAdd(&cur[binof(x)], 1u);
        size_t o = (size_t)b * NPTS + pos;
        g_bx[o] = x; g_by[o] = y; g_bz[o] = z;
        g_bidx[o] = (unsigned short)(base + i);
    }
}

// Sort each 256-pt x-group by y; emit exact per-half y bounds.
__global__ void ysort_kernel() {
    __shared__ float sx[256], sy[256], sz[256];
    __shared__ unsigned short si[256];
    __shared__ unsigned long long key[256];
    const int b = blockIdx.x / NGR, g = blockIdx.x % NGR;
    const int tid = threadIdx.x;
    const size_t base = (size_t)b * NPTS + g * 256;

    float y = g_by[base + tid];
    sx[tid] = g_bx[base + tid];
    sy[tid] = y;
    sz[tid] = g_bz[base + tid];
    si[tid] = g_bidx[base + tid];
    unsigned e = __float_as_uint(y);
    e = (e & 0x80000000u) ? ~e : (e | 0x80000000u);   // order-preserving
    key[tid] = ((unsigned long long)e << 32) | (unsigned)tid;
    __syncthreads();

    for (int k = 2; k <= 256; k <<= 1) {
        for (int j = k >> 1; j > 0; j >>= 1) {
            int ixj = tid ^ j;
            if (ixj > tid) {
                unsigned long long a0 = key[tid], a1 = key[ixj];
                bool up = ((tid & k) == 0);
                if ((a0 > a1) == up) { key[tid] = a1; key[ixj] = a0; }
            }
            __syncthreads();
        }
    }

    int src = (int)(key[tid] & 0xffu);
    g_bx[base + tid] = sx[src];
    g_by[base + tid] = sy[src];
    g_bz[base + tid] = sz[src];
    g_bidx[base + tid] = si[src];
    if (tid == 0)   g_cymin[b * NCHK + 2 * g]     = sy[(int)(key[0]   & 0xffu)];
    if (tid == 127) g_cymax[b * NCHK + 2 * g]     = sy[(int)(key[127] & 0xffu)];
    if (tid == 128) g_cymin[b * NCHK + 2 * g + 1] = sy[(int)(key[128] & 0xffu)];
    if (tid == 255) g_cymax[b * NCHK + 2 * g + 1] = sy[(int)(key[255] & 0xffu)];
}

// ------------------------------------------------------------ knn utils ----
__device__ __forceinline__ float sqdist(float qx, float qy, float qz,
                                        float x, float y, float z) {
    // No FMA contraction: matches reference (diff*diff then sum) bit-exactly.
    float dx = qx - x, dy = qy - y, dz = qz - z;
    return __fadd_rn(__fadd_rn(__fmul_rn(dx, dx), __fmul_rn(dy, dy)),
                     __fmul_rn(dz, dz));
}

__device__ __forceinline__ void warp_sort32(unsigned long long& v, int lane) {
    #pragma unroll
    for (int k = 2; k <= 32; k <<= 1) {
        #pragma unroll
        for (int j = k >> 1; j > 0; j >>= 1) {
            unsigned long long o = __shfl_xor_sync(FULLMASK, v, j);
            bool keepMin = (((lane & k) == 0) == ((lane & j) == 0));
            bool less = v < o;
            v = (less == keepMin) ? v : o;
        }
    }
}

__device__ __forceinline__ void warp_merge(unsigned long long& best,
                                           unsigned long long p, int lane) {
    unsigned long long bo = __shfl_sync(FULLMASK, p, 31 - lane);
    unsigned long long v = (best < bo) ? best : bo;
    #pragma unroll
    for (int j = 16; j > 0; j >>= 1) {
        unsigned long long o = __shfl_xor_sync(FULLMASK, v, j);
        bool lower = (lane & j) == 0;
        bool less = v < o;
        v = (less == lower) ? v : o;
    }
    best = v;
}

// ----------------------------------------------------------------- knn ----
__global__ __launch_bounds__(KNN_THREADS, 12)
void knn_kernel(const float* __restrict__ new_xyz) {
    __shared__ float sgxmin[NGR], sgxmax[NGR], scymin[NCHK], scymax[NCHK];
    __shared__ unsigned long long sbuf[QPB][BUFSZ];

    const int blocks_per_batch = NQUERY / QPB;   // 512
    const int b    = blockIdx.x / blocks_per_batch;
    const int qblk = blockIdx.x % blocks_per_batch;

    if (threadIdx.x < NCHK) {
        scymin[threadIdx.x] = g_cymin[b * NCHK + threadIdx.x];
        scymax[threadIdx.x] = g_cymax[b * NCHK + threadIdx.x];
        if (threadIdx.x < NGR) {
            sgxmin[threadIdx.x] = g_gxmin[b * NGR + threadIdx.x];
            sgxmax[threadIdx.x] = g_gxmax[b * NGR + threadIdx.x];
        }
    }
    __syncthreads();

    const int w    = threadIdx.x >> 5;
    const int lane = threadIdx.x & 31;
    const int q    = qblk * QPB + w;
    unsigned long long* buf = sbuf[w];

    const float* bxp = g_bx + (size_t)b * NPTS;
    const float* byp = g_by + (size_t)b * NPTS;
    const float* bzp = g_bz + (size_t)b * NPTS;
    const unsigned short* bip = g_bidx + (size_t)b * NPTS;
    const float4* px = (const float4*)bxp;
    const float4* py = (const float4*)byp;
    const float4* pz = (const float4*)bzp;
    const uint2*  pi = (const uint2*)bip;

    const float* nq = new_xyz + ((size_t)b * NQUERY + q) * 3;
    const float qx = __ldg(nq), qy = __ldg(nq + 1), qz = __ldg(nq + 2);

    unsigned long long best = ~0ULL;
    unsigned thrBits = 0xffffffffu;
    int cnt = 0;
    const unsigned lmask = (1u << lane) - 1u;

    // ---- append one chunk's candidates (optionally masking [ms, ms+32)) ----
    auto scan_chunk = [&](int c, int ms) {
        const int e0 = c * 32 + lane;
        float4 X = __ldg(px + e0);
        float4 Y = __ldg(py + e0);
        float4 Z = __ldg(pz + e0);

        unsigned u0 = __float_as_uint(sqdist(qx, qy, qz, X.x, Y.x, Z.x));
        unsigned u1 = __float_as_uint(sqdist(qx, qy, qz, X.y, Y.y, Z.y));
        unsigned u2 = __float_as_uint(sqdist(qx, qy, qz, X.z, Y.z, Z.z));
        unsigned u3 = __float_as_uint(sqdist(qx, qy, qz, X.w, Y.w, Z.w));

        if (ms >= 0) {                    // bootstrap-duplicate mask
            const int i0 = c * 128 + lane * 4;
            if ((unsigned)(i0 + 0 - ms) < 32u) u0 = 0xffffffffu;
            if ((unsigned)(i0 + 1 - ms) < 32u) u1 = 0xffffffffu;
            if ((unsigned)(i0 + 2 - ms) < 32u) u2 = 0xffffffffu;
            if ((unsigned)(i0 + 3 - ms) < 32u) u3 = 0xffffffffu;
        }

        unsigned mn = min(min(u0, u1), min(u2, u3));
        if (!__ballot_sync(FULLMASK, mn <= thrBits)) return;

        uint2 pk = __ldg(pi + e0);
        unsigned m0 = __ballot_sync(FULLMASK, u0 <= thrBits);
        if (m0) {
            if ((m0 >> lane) & 1u)
                buf[cnt + __popc(m0 & lmask)] =
                    ((unsigned long long)u0 << 32) | (pk.x & 0xffffu);
            cnt += __popc(m0);
        }
        unsigned m1 = __ballot_sync(FULLMASK, u1 <= thrBits);
        if (m1) {
            if ((m1 >> lane) & 1u)
                buf[cnt + __popc(m1 & lmask)] =
                    ((unsigned long long)u1 << 32) | (pk.x >> 16);
            cnt += __popc(m1);
        }
        unsigned m2 = __ballot_sync(FULLMASK, u2 <= thrBits);
        if (m2) {
            if ((m2 >> lane) & 1u)
                buf[cnt + __popc(m2 & lmask)] =
                    ((unsigned long long)u2 << 32) | (pk.y & 0xffffu);
            cnt += __popc(m2);
        }
        unsigned m3 = __ballot_sync(FULLMASK, u3 <= thrBits);
        if (m3) {
            if ((m3 >> lane) & 1u)
                buf[cnt + __popc(m3 & lmask)] =
                    ((unsigned long long)u3 << 32) | (pk.y >> 16);
            cnt += __popc(m3);
        }

        while (cnt >= 32) {               // drain (LIFO)
            __syncwarp(FULLMASK);
            unsigned long long v = buf[cnt - 32 + lane];
            cnt -= 32;
            warp_sort32(v, lane);
            warp_merge(best, v, lane);
            thrBits = (unsigned)(__shfl_sync(FULLMASK, best, 31) >> 32);
        }
    };

    const int pos0 = __ldg(&g_binstart[b * NBINS + binof(qx)]);
    const int g0 = min(pos0 >> 8, NGR - 1);

    // pick bootstrap half = the y-closer half of the query's own group
    const int ca = 2 * g0, cbh = 2 * g0 + 1;
    float dya = fmaxf(fmaxf(__fsub_rn(scymin[ca], qy),
                            __fsub_rn(qy, scymax[ca])), 0.0f);
    float dyb = fmaxf(fmaxf(__fsub_rn(scymin[cbh], qy),
                            __fsub_rn(qy, scymax[cbh])), 0.0f);
    const int cb = (dya <= dyb) ? ca : cbh;      // bootstrap half
    const int co = (dya <= dyb) ? cbh : ca;      // other half

    {   // bootstrap: 32 contiguous y-nearest points of cb (y-sorted)
        int lo = cb * 128, hi = lo + 128;
        while (lo < hi) {
            int m = (lo + hi) >> 1;
            if (byp[m] < qy) lo = m + 1; else hi = m;
        }
        int start = min(max(lo - 16, cb * 128), cb * 128 + 96);
        int pt = start + lane;
        float X = __ldg(bxp + pt), Y = __ldg(byp + pt), Z = __ldg(bzp + pt);
        unsigned short id = __ldg(bip + pt);
        unsigned long long v =
            ((unsigned long long)__float_as_uint(sqdist(qx, qy, qz, X, Y, Z)) << 32)
            | (unsigned)id;
        warp_sort32(v, lane);
        best = v;                          // 32 sorted real keys
        thrBits = (unsigned)(__shfl_sync(FULLMASK, best, 31) >> 32);

        scan_chunk(cb, start);             // rest of own half, masked

        // other half of own group (dxb = 0)
        float dyo = fmaxf(fmaxf(__fsub_rn(scymin[co], qy),
                                __fsub_rn(qy, scymax[co])), 0.0f);
        if (!(__fmul_rn(__fmul_rn(dyo, dyo), STOP) > __uint_as_float(thrBits)))
            scan_chunk(co, -1);
    }

    // right phase (group x-bounds monotone -> break safe)
    for (int g = g0 + 1; g < NGR; g++) {
        float rb = fmaxf(__fsub_rn(sgxmin[g], qx), 0.0f);
        float rb2 = __fmul_rn(rb, rb);
        if (__fmul_rn(rb2, STOP) > __uint_as_float(thrBits)) break;
        #pragma unroll
        for (int h = 0; h < 2; h++) {
            int c = 2 * g + h;
            float dy = fmaxf(fmaxf(__fsub_rn(scymin[c], qy),
                                   __fsub_rn(qy, scymax[c])), 0.0f);
            float bound = __fadd_rn(rb2, __fmul_rn(dy, dy));
            if (!(__fmul_rn(bound, STOP) > __uint_as_float(thrBits)))
                scan_chunk(c, -1);
        }
    }
    // left phase
    for (int g = g0 - 1; g >= 0; g--) {
        float lb = fmaxf(__fsub_rn(qx, sgxmax[g]), 0.0f);
        float lb2 = __fmul_rn(lb, lb);
        if (__fmul_rn(lb2, STOP) > __uint_as_float(thrBits)) break;
        #pragma unroll
        for (int h = 0; h < 2; h++) {
            int c = 2 * g + h;
            float dy = fmaxf(fmaxf(__fsub_rn(scymin[c], qy),
                                   __fsub_rn(qy, scymax[c])), 0.0f);
            float bound = __fadd_rn(lb2, __fmul_rn(dy, dy));
            if (!(__fmul_rn(bound, STOP) > __uint_as_float(thrBits)))
                scan_chunk(c, -1);
        }
    }

    if (cnt > 0) {       // final flush
        __syncwarp(FULLMASK);
        unsigned long long v = (lane < cnt) ? buf[lane] : ~0ULL;
        warp_sort32(v, lane);
        warp_merge(best, v, lane);
    }

    g_knn_idx[((size_t)b * NQUERY + q) * NS + lane] =
        (int)(unsigned)(best & 0xffffffffu);
}

// -------------------------------------------------------------- gather ----
constexpr int OUT_CH = 3 + NCH;                // 67
constexpr int ELEMS  = NQUERY * NS;            // 65536 per (b, ch)
constexpr int NV     = ELEMS / 4;              // 16384 float4 per (b, ch)
constexpr int NGRP   = 17;
constexpr int GSPLIT = 2;
constexpr int GATHER_THREADS = 1024;
constexpr int GATHER_SMEM = (NPTS + NQUERY) * 16;   // 160 KB

__global__ __launch_bounds__(GATHER_THREADS, 1)
void gather_kernel(const float* __restrict__ xyz,
                   const float* __restrict__ new_xyz,
                   const float* __restrict__ feats,
                   float* __restrict__ out) {
    extern __shared__ float4 s4[];
    float4* srow = s4;            // [NPTS]
    float4* sq   = s4 + NPTS;     // [NQUERY] (group 0 only)

    const int half = blockIdx.x % GSPLIT;
    const int bg   = blockIdx.x / GSPLIT;
    const int b    = bg / NGRP;
    const int g    = bg % NGRP;
    const int tid  = threadIdx.x;

    if (g > 0) {
        const int f0 = 4 * (g - 1);
        const float* c0 = feats + ((size_t)b * NCH + f0) * NPTS;
        const float* c1 = c0 + NPTS;
        const float* c2 = c1 + NPTS;
        const float* c3 = c2 + NPTS;
        for (int i = tid; i < NPTS; i += GATHER_THREADS)
            srow[i] = make_float4(__ldg(c0 + i), __ldg(c1 + i),
                                  __ldg(c2 + i), __ldg(c3 + i));
    } else {
        const float* src = xyz + (size_t)b * NPTS * 3;
        for (int i = tid; i < NPTS; i += GATHER_THREADS)
            srow[i] = make_float4(src[3 * i], src[3 * i + 1], src[3 * i + 2], 0.0f);
        const float* qs = new_xyz + (size_t)b * NQUERY * 3;
        for (int i = tid; i < NQUERY; i += GATHER_THREADS)
            sq[i] = make_float4(qs[3 * i], qs[3 * i + 1], qs[3 * i + 2], 0.0f);
    }
    __syncthreads();

    const int4* idx4 = reinterpret_cast<const int4*>(g_knn_idx + (size_t)b * ELEMS);
    constexpr int NVH = NV / GSPLIT;            // 8192 per block
    const int e0 = half * NVH;

    if (g > 0) {
        const int ch0 = 3 + 4 * (g - 1);
        float4* o = reinterpret_cast<float4*>(out + ((size_t)b * OUT_CH + ch0) * ELEMS);
        #pragma unroll
        for (int it = 0; it < NVH / GATHER_THREADS; it++) {
            int e = e0 + it * GATHER_THREADS + tid;
            int4 n = idx4[e];
            float4 p0 = srow[n.x], p1 = srow[n.y], p2 = srow[n.z], p3 = srow[n.w];
            o[e]          = make_float4(p0.x, p1.x, p2.x, p3.x);
            o[e + NV]     = make_float4(p0.y, p1.y, p2.y, p3.y);
            o[e + 2 * NV] = make_float4(p0.z, p1.z, p2.z, p3.z);
            o[e + 3 * NV] = make_float4(p0.w, p1.w, p2.w, p3.w);
        }
    } else {
        float4* o = reinterpret_cast<float4*>(out + (size_t)b * OUT_CH * ELEMS);
        #pragma unroll
        for (int it = 0; it < NVH / GATHER_THREADS; it++) {
            int e = e0 + it * GATHER_THREADS + tid;
            int4 n = idx4[e];
            float4 p0 = srow[n.x], p1 = srow[n.y], p2 = srow[n.z], p3 = srow[n.w];
            float4 qv = sq[e >> 3];             // query = (4e)/32
            o[e]          = make_float4(__fsub_rn(p0.x, qv.x), __fsub_rn(p1.x, qv.x),
                                        __fsub_rn(p2.x, qv.x), __fsub_rn(p3.x, qv.x));
            o[e + NV]     = make_float4(__fsub_rn(p0.y, qv.y), __fsub_rn(p1.y, qv.y),
                                        __fsub_rn(p2.y, qv.y), __fsub_rn(p3.y, qv.y));
            o[e + 2 * NV] = make_float4(__fsub_rn(p0.z, qv.z), __fsub_rn(p1.z, qv.z),
                                        __fsub_rn(p2.z, qv.z), __fsub_rn(p3.z, qv.z));
        }
    }
}

// -------------------------------------------------------------- launch ----
extern "C" void kernel_launch(void* const* d_in, const int* in_sizes, int n_in,
                              void* d_out, int out_size) {
    const float* xyz      = (const float*)d_in[0];   // (4, 8192, 3) f32
    const float* new_xyz  = (const float*)d_in[1];   // (4, 2048, 3) f32
    // d_in[2], d_in[3]: components (int64) -- dead (LAMBDA = 0.5)
    const float* feats    = (const float*)d_in[4];   // (4, 64, 8192) f32
    float* out = (float*)d_out;                      // (4, 67, 2048, 32) f32

    cudaFuncSetAttribute(gather_kernel,
                         cudaFuncAttributeMaxDynamicSharedMemorySize, GATHER_SMEM);

    hist_kernel<<<BATCH * PARTS, 256>>>(xyz);
    scan_kernel<<<BATCH, 256>>>();
    scatter_kernel<<<BATCH * PARTS, 256>>>(xyz);
    ysort_kernel<<<BATCH * NGR, 256>>>();
    knn_kernel<<<BATCH * (NQUERY / QPB), KNN_THREADS>>>(new_xyz);
    gather_kernel<<<BATCH * NGRP * GSPLIT, GATHER_THREADS, GATHER_SMEM>>>(
        xyz, new_xyz, feats, out);
}